// round 4
// baseline (speedup 1.0000x reference)
#include <cuda_runtime.h>
#include <math.h>

#define NB 8
#define CC 256
#define HHH 56
#define WWW 56
#define SS 3136
#define CS 802816      // CC*SS
#define NCS 6422528    // NB*CC*SS

// ---------------- scratch (static device globals; no runtime alloc) ----------------
__device__ float g_t3[NCS];
__device__ float g_t5[NCS];
__device__ float g_t7[NCS];
__device__ float g_t17[NCS];
__device__ float g_t13[NCS];
__device__ float g_t8[NB * CC * CC];      // [b][i]
__device__ float g_AmatT[NB * CC * CC];   // [b][j]  (k-major A for mode2)
__device__ float g_t19[NB * CC * CC];     // [j][i]  (k-major A for mode1)
__device__ float g_w7t[9 * CC * CC];      // [tap*256 + c][o]  (k-major)
__device__ float g_w15t[CC * CC];         // [c][o]            (k-major)
__device__ float g_veff[CS];              // [c][s]
__device__ float g_t11[NB * SS];
__device__ float g_part[4 * NB * CC * CC]; // split-K partials

// ---------------- stage A: t3 = (p2*x)^2 ; t5 = softmax_h(roll(t3,1,-1)) ----------------
__global__ void __launch_bounds__(256) stageA(const float* __restrict__ x,
                                              const float* __restrict__ p2) {
    int plane = blockIdx.x;            // n*256 + c
    int c = plane & 255;
    const float* xp = x + (size_t)plane * SS;
    const float* pp = p2 + (size_t)c * SS;
    float* t3p = g_t3 + (size_t)plane * SS;
    float* t5p = g_t5 + (size_t)plane * SS;
    __shared__ float sm[SS];
    for (int i = threadIdx.x; i < SS; i += 256) {
        float v = pp[i] * xp[i];
        v *= v;
        sm[i] = v;
        t3p[i] = v;
    }
    __syncthreads();
    int wc = threadIdx.x;              // source column
    if (wc < WWW) {
        float mx = -1e30f;
        for (int h = 0; h < HHH; ++h) mx = fmaxf(mx, sm[h * WWW + wc]);
        float s = 0.f;
        for (int h = 0; h < HHH; ++h) {
            float e = __expf(sm[h * WWW + wc] - mx);
            sm[h * WWW + wc] = e;
            s += e;
        }
        float inv = 1.f / s;
        int wout = (wc + WWW - 1) % WWW;
        for (int h = 0; h < HHH; ++h) {
            int ho = h + 1; if (ho == HHH) ho = 0;
            t5p[ho * WWW + wout] = sm[h * WWW + wc] * inv;
        }
    }
}

// ---------------- prep: transpose w7 (C,9C) -> w7t[tap*256+c][o] ----------------
__global__ void prepW7(const float* __restrict__ w7) {
    int idx = blockIdx.x * 256 + threadIdx.x;     // over 9*256*256
    int o = idx & 255;
    int k = idx >> 8;                              // tap*256 + c
    int tap = k >> 8;
    int cc = k & 255;
    g_w7t[idx] = w7[o * 2304 + cc * 9 + tap];
}

// ---------------- prep: w15t[c][o] = w15[o][c] ----------------
__global__ void prepW15T(const float* __restrict__ w15) {
    int idx = blockIdx.x * 256 + threadIdx.x;   // c*256 + o
    int o = idx & 255;
    int c = idx >> 8;
    g_w15t[idx] = w15[o * 256 + c];
}

// ---------------- prep: veff[c,s] = sum_o w6[o,c]*p9[o,s]*p11[o] ----------------
__global__ void prepVeff(const float* __restrict__ w6, const float* __restrict__ p9,
                         const float* __restrict__ p11) {
    int idx = blockIdx.x * 256 + threadIdx.x;     // c*SS + s
    int s = idx % SS;
    int c = idx / SS;
    float acc = 0.f;
#pragma unroll
    for (int o = 0; o < 32; ++o)
        acc = fmaf(w6[o * CC + c], p9[o * SS + s] * p11[o], acc);
    g_veff[idx] = acc;
}

// ================== 128x128 tile / 8x8 microtile machinery ==================

#define GEMM_COMPUTE(buf)                                                     \
    _Pragma("unroll")                                                         \
    for (int kk = 0; kk < 8; ++kk) {                                          \
        float av[8], bv[8];                                                   \
        *(float4*)&av[0] = *(const float4*)&As[buf][kk][ty * 8];              \
        *(float4*)&av[4] = *(const float4*)&As[buf][kk][ty * 8 + 4];          \
        *(float4*)&bv[0] = *(const float4*)&Bs[buf][kk][tx * 8];              \
        *(float4*)&bv[4] = *(const float4*)&Bs[buf][kk][tx * 8 + 4];          \
        _Pragma("unroll")                                                     \
        for (int i = 0; i < 8; ++i)                                           \
            _Pragma("unroll")                                                 \
            for (int j = 0; j < 8; ++j)                                       \
                acc[i][j] = fmaf(av[i], bv[j], acc[i][j]);                    \
    }

// ---------------- t7: implicit GEMM conv, M=256, N=3136, K=9x256 ----------------
__global__ void __launch_bounds__(256, 2) convT7k(const float* __restrict__ x) {
    __shared__ float As[2][8][128];
    __shared__ float Bs[2][8][128];
    int n = blockIdx.z;
    int m0 = blockIdx.y * 128;
    int col0 = blockIdx.x * 128;
    int t = threadIdx.x;
    int tx = t & 15, ty = t >> 4;
    int ak = t >> 5, am4 = (t & 31) * 4;      // A loader
    int bp = t & 127, kb = (t >> 7) * 4;      // B loader
    int pglob = col0 + bp;
    bool pin = pglob < SS;
    int h = pglob / 56, w = pglob - h * 56;
    const float* xn = x + (size_t)n * CS;

    float4 a_reg; float b_reg[4];
    float acc[8][8] = {};

#define CONV_LOAD(kg) {                                                       \
    int tap = (kg) >> 8; int kin = (kg) & 255;                                \
    a_reg = *(const float4*)&g_w7t[(size_t)((kg) + ak) * 256 + m0 + am4];     \
    int dy = (tap / 3) * 3 - 3, dxx = (tap % 3) * 3 - 3;                      \
    int hh = h + dy, ww = w + dxx;                                            \
    bool valid = pin && ((unsigned)hh < 56u) && ((unsigned)ww < 56u);         \
    int poff = hh * 56 + ww;                                                  \
    _Pragma("unroll")                                                         \
    for (int i = 0; i < 4; ++i)                                               \
        b_reg[i] = valid ? xn[(size_t)(kin + kb + i) * SS + poff] : 0.f; }

#define TILE_STORE(buf) {                                                     \
    *(float4*)&As[buf][ak][am4] = a_reg;                                      \
    _Pragma("unroll")                                                         \
    for (int i = 0; i < 4; ++i) Bs[buf][kb + i][bp] = b_reg[i]; }

    CONV_LOAD(0);
    TILE_STORE(0);
    int buf = 0;
#pragma unroll 1
    for (int kg = 0; kg < 2304; kg += 8) {
        __syncthreads();
        bool more = (kg + 8) < 2304;
        if (more) CONV_LOAD(kg + 8);
        GEMM_COMPUTE(buf);
        if (more) { TILE_STORE(buf ^ 1); buf ^= 1; }
    }

    float* t7n = g_t7 + (size_t)n * CS;
#pragma unroll
    for (int i = 0; i < 8; ++i) {
        int row = m0 + ty * 8 + i;
        int c0 = col0 + tx * 8;
        if (c0 < SS)
            *(float4*)&t7n[(size_t)row * SS + c0] =
                make_float4(acc[i][0], acc[i][1], acc[i][2], acc[i][3]);
        if (c0 + 4 < SS)
            *(float4*)&t7n[(size_t)row * SS + c0 + 4] =
                make_float4(acc[i][4], acc[i][5], acc[i][6], acc[i][7]);
    }
#undef CONV_LOAD
}

// ---------------- NN GEMM (A k-major [K=256][M=256]), 128x128 tiles ----------------
// MODE 0: B = x rolled(+1,h); out t17 = t3 - acc                 (N=3136)
// MODE 1: B = t13; out = s_c*acc + t7*t17 -> final output        (N=3136)
// MODE 2: B = t8 (ld 256); out = s_hw*acc -> t19 natural layout  (N=256)
template <int MODE>
__global__ void __launch_bounds__(256, 2) gemm128(const float* __restrict__ A,
                                                  const float* __restrict__ B,
                                                  float* __restrict__ Out,
                                                  const float* __restrict__ E1,
                                                  const float* __restrict__ E2,
                                                  size_t strA, size_t strB) {
    constexpr int LDB = (MODE == 2) ? 256 : SS;
    constexpr int NMAX = (MODE == 2) ? 256 : SS;
    constexpr size_t strO = (MODE == 2) ? (size_t)65536 : (size_t)CS;
    __shared__ float As[2][8][128];
    __shared__ float Bs[2][8][128];
    int n = blockIdx.z;
    int m0 = blockIdx.y * 128;
    int col0 = blockIdx.x * 128;
    const float* An = A + (size_t)n * strA;
    const float* Bn = B + (size_t)n * strB;
    int t = threadIdx.x;
    int tx = t & 15, ty = t >> 4;
    int ak = t >> 5, am4 = (t & 31) * 4;
    int bp = t & 127, kb = (t >> 7) * 4;
    int pglob = col0 + bp;
    bool pin = pglob < NMAX;
    int poff;
    if (MODE == 0) {
        int hh = pglob / 56, ww = pglob - hh * 56;
        int h2 = hh ? hh - 1 : 55;        // t14[h] = x[h-1 mod 56]
        poff = h2 * 56 + ww;
    } else {
        poff = pglob;
    }
    float4 a_reg; float b_reg[4];
    float acc[8][8] = {};

#define NN_LOAD(k0) {                                                         \
    a_reg = *(const float4*)&An[(size_t)((k0) + ak) * 256 + m0 + am4];        \
    _Pragma("unroll")                                                         \
    for (int i = 0; i < 4; ++i)                                               \
        b_reg[i] = pin ? Bn[(size_t)((k0) + kb + i) * LDB + poff] : 0.f; }

    NN_LOAD(0);
    TILE_STORE(0);
    int buf = 0;
#pragma unroll 1
    for (int k0 = 0; k0 < 256; k0 += 8) {
        __syncthreads();
        bool more = (k0 + 8) < 256;
        if (more) NN_LOAD(k0 + 8);
        GEMM_COMPUTE(buf);
        if (more) { TILE_STORE(buf ^ 1); buf ^= 1; }
    }
#undef NN_LOAD

    float* on = Out + (size_t)n * strO;
    if (MODE == 0) {
        const float* e1 = E1 + (size_t)n * CS;   // t3
#pragma unroll
        for (int i = 0; i < 8; ++i) {
            size_t base = (size_t)(m0 + ty * 8 + i) * SS;
            int c0 = col0 + tx * 8;
            if (c0 < SS) {
                float4 e = *(const float4*)&e1[base + c0];
                *(float4*)&on[base + c0] = make_float4(e.x - acc[i][0], e.y - acc[i][1],
                                                       e.z - acc[i][2], e.w - acc[i][3]);
            }
            if (c0 + 4 < SS) {
                float4 e = *(const float4*)&e1[base + c0 + 4];
                *(float4*)&on[base + c0 + 4] = make_float4(e.x - acc[i][4], e.y - acc[i][5],
                                                           e.z - acc[i][6], e.w - acc[i][7]);
            }
        }
    } else if (MODE == 1) {
        const float* e1 = E1 + (size_t)n * CS;   // t7
        const float* e2 = E2 + (size_t)n * CS;   // t17
        const float sc = 0.0625f;                // 1/sqrt(256)
#pragma unroll
        for (int i = 0; i < 8; ++i) {
            size_t base = (size_t)(m0 + ty * 8 + i) * SS;
            int c0 = col0 + tx * 8;
            if (c0 < SS) {
                float4 a7 = *(const float4*)&e1[base + c0];
                float4 a17 = *(const float4*)&e2[base + c0];
                float4 r;
                r.x = fmaf(sc, acc[i][0], a7.x * a17.x);
                r.y = fmaf(sc, acc[i][1], a7.y * a17.y);
                r.z = fmaf(sc, acc[i][2], a7.z * a17.z);
                r.w = fmaf(sc, acc[i][3], a7.w * a17.w);
                *(float4*)&on[base + c0] = r;
            }
            if (c0 + 4 < SS) {
                float4 a7 = *(const float4*)&e1[base + c0 + 4];
                float4 a17 = *(const float4*)&e2[base + c0 + 4];
                float4 r;
                r.x = fmaf(sc, acc[i][4], a7.x * a17.x);
                r.y = fmaf(sc, acc[i][5], a7.y * a17.y);
                r.z = fmaf(sc, acc[i][6], a7.z * a17.z);
                r.w = fmaf(sc, acc[i][7], a7.w * a17.w);
                *(float4*)&on[base + c0 + 4] = r;
            }
        }
    } else {
        const float shw = 1.f / 56.f;
#pragma unroll
        for (int i = 0; i < 8; ++i) {
            size_t base = (size_t)(m0 + ty * 8 + i) * 256;
            int c0 = col0 + tx * 8;
            *(float4*)&on[base + c0] = make_float4(acc[i][0] * shw, acc[i][1] * shw,
                                                   acc[i][2] * shw, acc[i][3] * shw);
            *(float4*)&on[base + c0 + 4] = make_float4(acc[i][4] * shw, acc[i][5] * shw,
                                                       acc[i][6] * shw, acc[i][7] * shw);
        }
    }
}

// ---------------- NT GEMM split-K: Part[m,n] += sum_{k in chunk} A[m,k]*B[n,k] ----------------
// M=N=256, K=3136 split into 4 chunks of 784. grid (2, 2, NB*4).
__global__ void __launch_bounds__(256, 2) gemmNT128(const float* __restrict__ A,
                                                    const float* __restrict__ B,
                                                    float* __restrict__ Part,
                                                    size_t strA, size_t strB) {
    __shared__ float As[2][8][128];
    __shared__ float Bs[2][8][128];
    int z = blockIdx.z;
    int n = z >> 2, split = z & 3;
    int kbeg = split * 784;
    const float* An = A + (size_t)n * strA;
    const float* Bn = B + (size_t)n * strB;
    float* P = Part + (size_t)z * 65536;
    int m0 = blockIdx.y * 128, n0 = blockIdx.x * 128;
    int t = threadIdx.x;
    int tx = t & 15, ty = t >> 4;
    int row = t & 127, kq = (t >> 7) * 4;
    float4 a_reg, b_reg;
    float acc[8][8] = {};

#define NT_LOAD(k0) {                                                         \
    a_reg = *(const float4*)&An[(size_t)(m0 + row) * SS + (k0) + kq];         \
    b_reg = *(const float4*)&Bn[(size_t)(n0 + row) * SS + (k0) + kq]; }

#define NT_STORE(buf) {                                                       \
    As[buf][kq + 0][row] = a_reg.x; As[buf][kq + 1][row] = a_reg.y;           \
    As[buf][kq + 2][row] = a_reg.z; As[buf][kq + 3][row] = a_reg.w;           \
    Bs[buf][kq + 0][row] = b_reg.x; Bs[buf][kq + 1][row] = b_reg.y;           \
    Bs[buf][kq + 2][row] = b_reg.z; Bs[buf][kq + 3][row] = b_reg.w; }

    NT_LOAD(kbeg);
    NT_STORE(0);
    int buf = 0;
#pragma unroll 1
    for (int k0 = kbeg; k0 < kbeg + 784; k0 += 8) {
        __syncthreads();
        bool more = (k0 + 8) < kbeg + 784;
        if (more) NT_LOAD(k0 + 8);
        GEMM_COMPUTE(buf);
        if (more) { NT_STORE(buf ^ 1); buf ^= 1; }
    }
#undef NT_LOAD
#undef NT_STORE

#pragma unroll
    for (int i = 0; i < 8; ++i) {
        size_t base = (size_t)(m0 + ty * 8 + i) * 256 + n0 + tx * 8;
        *(float4*)&P[base] = make_float4(acc[i][0], acc[i][1], acc[i][2], acc[i][3]);
        *(float4*)&P[base + 4] = make_float4(acc[i][4], acc[i][5], acc[i][6], acc[i][7]);
    }
}

// ---------------- reduce split-K partials (optionally transposed write) ----------------
template <bool TRANS>
__global__ void ntReduce(const float* __restrict__ Part, float* __restrict__ Out,
                         float scale) {
    int idx = blockIdx.x * 256 + threadIdx.x;   // over NB*65536
    int nb = idx >> 16;
    int r = idx & 65535;
    float s = 0.f;
#pragma unroll
    for (int sp = 0; sp < 4; ++sp)
        s += Part[(size_t)(nb * 4 + sp) * 65536 + r];
    s *= scale;
    if (TRANS) {
        int m = r >> 8, col = r & 255;
        Out[(size_t)nb * 65536 + col * 256 + m] = s;
    } else {
        Out[(size_t)nb * 65536 + r] = s;
    }
}

// ---------------- t11[n,s] = sum_c t3[n,c,s]*veff[c,s] ----------------
__global__ void calcT11() {
    int idx = blockIdx.x * 256 + threadIdx.x;   // n*SS + s
    int n = idx / SS;
    int s = idx - n * SS;
    const float* t3n = g_t3 + (size_t)n * CS + s;
    const float* vf = g_veff + s;
    float acc = 0.f;
#pragma unroll 8
    for (int c = 0; c < CC; ++c)
        acc = fmaf(t3n[(size_t)c * SS], vf[(size_t)c * SS], acc);
    g_t11[idx] = acc;
}

// ---------------- t13 = t11 - dwconv3x1_d2(max(t5,t7)) ----------------
__global__ void calcT13(const float* __restrict__ w12) {
    int idx = blockIdx.x * 256 + threadIdx.x;   // n*CC*SS + c*SS + p
    int p = idx % SS;
    int nc = idx / SS;
    int c = nc & 255;
    int n = nc >> 8;
    int h = p / 56, w = p - h * 56;
    float acc = 0.f;
#pragma unroll
    for (int r = 0; r < 3; ++r) {
        int hh = h + 2 * r - 2;
        if ((unsigned)hh < 56u) {
            size_t q = (size_t)nc * SS + hh * 56 + w;
            acc = fmaf(w12[c * 3 + r], fmaxf(g_t5[q], g_t7[q]), acc);
        }
    }
    g_t13[idx] = g_t11[(size_t)n * SS + p] - acc;
}

// ---------------- launch ----------------
extern "C" void kernel_launch(void* const* d_in, const int* in_sizes, int n_in,
                              void* d_out, int out_size) {
    const float* x   = (const float*)d_in[0];
    const float* p2  = (const float*)d_in[1];
    const float* w6  = (const float*)d_in[2];
    const float* w7  = (const float*)d_in[3];
    const float* p9  = (const float*)d_in[4];
    const float* p11 = (const float*)d_in[5];
    const float* w12 = (const float*)d_in[6];
    const float* w15 = (const float*)d_in[7];
    const float* p16 = (const float*)d_in[8];
    float* out = (float*)d_out;

    void *t3p, *t5p, *t7p, *t17p, *t13p, *t8p, *AmatTp, *t19p, *w15tp, *partp;
    cudaGetSymbolAddress(&t3p, g_t3);
    cudaGetSymbolAddress(&t5p, g_t5);
    cudaGetSymbolAddress(&t7p, g_t7);
    cudaGetSymbolAddress(&t17p, g_t17);
    cudaGetSymbolAddress(&t13p, g_t13);
    cudaGetSymbolAddress(&t8p, g_t8);
    cudaGetSymbolAddress(&AmatTp, g_AmatT);
    cudaGetSymbolAddress(&t19p, g_t19);
    cudaGetSymbolAddress(&w15tp, g_w15t);
    cudaGetSymbolAddress(&partp, g_part);

    // stage A: t3, t5
    stageA<<<NB * CC, 256>>>(x, p2);
    // weight prep (independent)
    prepW7<<<9 * CC, 256>>>(w7);
    prepW15T<<<CC, 256>>>(w15);
    prepVeff<<<SS, 256>>>(w6, p9, p11);
    // t7: big implicit-GEMM conv
    convT7k<<<dim3(25, 2, NB), 256>>>(x);
    // t17 = t3 - w15 @ roll(x, +1, h)
    gemm128<0><<<dim3(25, 2, NB), 256>>>((const float*)w15tp, x, (float*)t17p,
                                         (const float*)t3p, nullptr, 0, (size_t)CS);
    // t8 = s_hw * t5 @ t3^T   (split-K 4 + reduce)
    gemmNT128<<<dim3(2, 2, NB * 4), 256>>>((const float*)t5p, (const float*)t3p,
                                           (float*)partp, (size_t)CS, (size_t)CS);
    ntReduce<false><<<NB * 256, 256>>>((const float*)partp, (float*)t8p, 1.f / 56.f);
    // t11, t13
    calcT11<<<(NB * SS) / 256, 256>>>();
    calcT13<<<NCS / 256, 256>>>(w12);
    // AmatT = (t17 @ p16^T)^T  (split-K 4 + transposed reduce)
    gemmNT128<<<dim3(2, 2, NB * 4), 256>>>((const float*)t17p, p16,
                                           (float*)partp, (size_t)CS, (size_t)0);
    ntReduce<true><<<NB * 256, 256>>>((const float*)partp, (float*)AmatTp, 1.f);
    // t19[j][i] = s_hw * (Amat @ t8)[j][i]  (natural layout = k-major for mode1)
    gemm128<2><<<dim3(2, 2, NB), 256>>>((const float*)AmatTp, (const float*)t8p,
                                        (float*)t19p, nullptr, nullptr,
                                        (size_t)65536, (size_t)65536);
    // out = s_c * t19^T @ t13 + t7 * t17
    gemm128<1><<<dim3(25, 2, NB), 256>>>((const float*)t19p, (const float*)t13p, out,
                                         (const float*)t7p, (const float*)t17p,
                                         (size_t)65536, (size_t)CS);
}

// round 5
// speedup vs baseline: 1.2258x; 1.2258x over previous
#include <cuda_runtime.h>
#include <math.h>

#define NB 8
#define CC 256
#define HHH 56
#define WWW 56
#define SS 3136
#define CS 802816      // CC*SS
#define NCS 6422528    // NB*CC*SS

// ---------------- scratch (static device globals; no runtime alloc) ----------------
__device__ float g_t3[NCS];
__device__ float g_t5[NCS];
__device__ float g_t7[NCS];
__device__ float g_t17[NCS];
__device__ float g_t13[NCS];
__device__ float g_t8[NB * CC * CC];      // [c][d]
__device__ float g_Amat[NB * CC * CC];    // [c][b]
__device__ float g_t19[NB * CC * CC];     // natural R=Amat@t8 layout (k-major A for final)
__device__ float g_w7t[9 * CC * CC];      // [tap*256 + c][o]  (k-major)
__device__ float g_w15t[CC * CC];         // [c][o]            (k-major)
__device__ float g_veff[CS];              // [c][s]
__device__ float g_t11[NB * SS];

// ---------------- stage A: t3 = (p2*x)^2 ; t5 = softmax_h(roll(t3,1,-1)) ----------------
__global__ void __launch_bounds__(256) stageA(const float* __restrict__ x,
                                              const float* __restrict__ p2) {
    int plane = blockIdx.x;            // n*256 + c
    int c = plane & 255;
    const float* xp = x + (size_t)plane * SS;
    const float* pp = p2 + (size_t)c * SS;
    float* t3p = g_t3 + (size_t)plane * SS;
    float* t5p = g_t5 + (size_t)plane * SS;
    __shared__ float sm[SS];
    for (int i = threadIdx.x; i < SS; i += 256) {
        float v = pp[i] * xp[i];
        v *= v;
        sm[i] = v;
        t3p[i] = v;
    }
    __syncthreads();
    int wc = threadIdx.x;              // source column
    if (wc < WWW) {
        float mx = -1e30f;
        for (int h = 0; h < HHH; ++h) mx = fmaxf(mx, sm[h * WWW + wc]);
        float s = 0.f;
        for (int h = 0; h < HHH; ++h) {
            float e = __expf(sm[h * WWW + wc] - mx);
            sm[h * WWW + wc] = e;
            s += e;
        }
        float inv = 1.f / s;
        int wout = (wc + WWW - 1) % WWW;
        for (int h = 0; h < HHH; ++h) {
            int ho = h + 1; if (ho == HHH) ho = 0;
            t5p[ho * WWW + wout] = sm[h * WWW + wc] * inv;
        }
    }
}

// ---------------- prep: transpose w7 (C,9C) -> w7t[tap*256+c][o] ----------------
__global__ void prepW7(const float* __restrict__ w7) {
    int idx = blockIdx.x * 256 + threadIdx.x;     // over 9*256*256
    int o = idx & 255;
    int k = idx >> 8;                              // tap*256 + c
    int tap = k >> 8;
    int cc = k & 255;
    g_w7t[idx] = w7[o * 2304 + cc * 9 + tap];
}

// ---------------- prep: w15t[c][o] = w15[o][c] ----------------
__global__ void prepW15T(const float* __restrict__ w15) {
    int idx = blockIdx.x * 256 + threadIdx.x;   // c*256 + o
    int o = idx & 255;
    int c = idx >> 8;
    g_w15t[idx] = w15[o * 256 + c];
}

// ---------------- prep: veff[c,s] = sum_o w6[o,c]*p9[o,s]*p11[o] ----------------
__global__ void prepVeff(const float* __restrict__ w6, const float* __restrict__ p9,
                         const float* __restrict__ p11) {
    int idx = blockIdx.x * 256 + threadIdx.x;     // c*SS + s
    int s = idx % SS;
    int c = idx / SS;
    float acc = 0.f;
#pragma unroll
    for (int o = 0; o < 32; ++o)
        acc = fmaf(w6[o * CC + c], p9[o * SS + s] * p11[o], acc);
    g_veff[idx] = acc;
}

// ================== 128x64 tile / 8x4 microtile machinery ==================
// 256 threads: ty = t>>4 (16 m-groups of 8 rows), tx = t&15 (16 n-groups of 4 cols)
// A smem: [8][128] k-major; B smem: [8][64]

#define MT_COMPUTE(buf)                                                       \
    _Pragma("unroll")                                                         \
    for (int kk = 0; kk < 8; ++kk) {                                          \
        float av[8], bv[4];                                                   \
        *(float4*)&av[0] = *(const float4*)&As[buf][kk][ty * 8];              \
        *(float4*)&av[4] = *(const float4*)&As[buf][kk][ty * 8 + 4];          \
        *(float4*)&bv[0] = *(const float4*)&Bs[buf][kk][tx * 4];              \
        _Pragma("unroll")                                                     \
        for (int i = 0; i < 8; ++i)                                           \
            _Pragma("unroll")                                                 \
            for (int j = 0; j < 4; ++j)                                       \
                acc[i][j] = fmaf(av[i], bv[j], acc[i][j]);                    \
    }

#define MT_STORE(buf) {                                                       \
    *(float4*)&As[buf][ak][am4] = a_reg;                                      \
    Bs[buf][kb + 0][bp] = b_reg[0];                                           \
    Bs[buf][kb + 1][bp] = b_reg[1]; }

// ---------------- t7: implicit GEMM conv, M=256, N=3136, K=9x256 ----------------
__global__ void __launch_bounds__(256) convT7k(const float* __restrict__ x) {
    __shared__ float As[2][8][128];
    __shared__ float Bs[2][8][64];
    int n = blockIdx.z;
    int m0 = blockIdx.y * 128;
    int col0 = blockIdx.x * 64;
    int t = threadIdx.x;
    int tx = t & 15, ty = t >> 4;
    int ak = t >> 5, am4 = (t & 31) * 4;      // A loader: row ak, 4 cols
    int bp = t & 63, kb = (t >> 6) * 2;       // B loader: pixel bp, rows kb,kb+1
    int pglob = col0 + bp;                    // < 3136 always (49*64)
    int h = pglob / 56, w = pglob - h * 56;
    const float* xn = x + (size_t)n * CS;

    float4 a_reg; float b_reg[2];
    float acc[8][4] = {};

#define CONV_LOAD(kg) {                                                       \
    int tap = (kg) >> 8; int kin = (kg) & 255;                                \
    a_reg = *(const float4*)&g_w7t[(size_t)((kg) + ak) * 256 + m0 + am4];     \
    int dy = (tap / 3) * 3 - 3, dxx = (tap % 3) * 3 - 3;                      \
    int hh = h + dy, ww = w + dxx;                                            \
    bool valid = ((unsigned)hh < 56u) && ((unsigned)ww < 56u);                \
    int poff = hh * 56 + ww;                                                  \
    b_reg[0] = valid ? xn[(size_t)(kin + kb + 0) * SS + poff] : 0.f;          \
    b_reg[1] = valid ? xn[(size_t)(kin + kb + 1) * SS + poff] : 0.f; }

    CONV_LOAD(0);
    MT_STORE(0);
#pragma unroll 1
    for (int kg = 0; kg < 2304; kg += 16) {
        __syncthreads();
        CONV_LOAD(kg + 8);
        MT_COMPUTE(0);
        MT_STORE(1);
        __syncthreads();
        bool more = (kg + 16) < 2304;
        if (more) CONV_LOAD(kg + 16);
        MT_COMPUTE(1);
        if (more) MT_STORE(0);
    }
#undef CONV_LOAD

    float* t7n = g_t7 + (size_t)n * CS;
    int c0 = col0 + tx * 4;
#pragma unroll
    for (int i = 0; i < 8; ++i) {
        int row = m0 + ty * 8 + i;
        *(float4*)&t7n[(size_t)row * SS + c0] =
            make_float4(acc[i][0], acc[i][1], acc[i][2], acc[i][3]);
    }
}

// ---------------- NN GEMM, A k-major [256][256], N=3136, 128x64 tiles ----------------
// MODE 0: A=w15t, B = x rolled(+1,h); out t17 = t3 - acc
// MODE 1: A=t19 (k-major), B = t13; out = s_c*acc + t7*t17 -> final output
template <int MODE>
__global__ void __launch_bounds__(256) gemmBig(const float* __restrict__ A,
                                               const float* __restrict__ B,
                                               float* __restrict__ Out,
                                               const float* __restrict__ E1,
                                               const float* __restrict__ E2,
                                               size_t strA, size_t strB) {
    __shared__ float As[2][8][128];
    __shared__ float Bs[2][8][64];
    int n = blockIdx.z;
    int m0 = blockIdx.y * 128;
    int col0 = blockIdx.x * 64;
    const float* An = A + (size_t)n * strA;
    const float* Bn = B + (size_t)n * strB;
    int t = threadIdx.x;
    int tx = t & 15, ty = t >> 4;
    int ak = t >> 5, am4 = (t & 31) * 4;
    int bp = t & 63, kb = (t >> 6) * 2;
    int pglob = col0 + bp;
    int poff;
    if (MODE == 0) {
        int hh = pglob / 56, ww = pglob - hh * 56;
        int h2 = hh ? hh - 1 : 55;        // t14[h] = x[h-1 mod 56]
        poff = h2 * 56 + ww;
    } else {
        poff = pglob;
    }
    float4 a_reg; float b_reg[2];
    float acc[8][4] = {};

#define NN_LOAD(k0) {                                                         \
    a_reg = *(const float4*)&An[(size_t)((k0) + ak) * 256 + m0 + am4];        \
    b_reg[0] = Bn[(size_t)((k0) + kb + 0) * SS + poff];                       \
    b_reg[1] = Bn[(size_t)((k0) + kb + 1) * SS + poff]; }

    NN_LOAD(0);
    MT_STORE(0);
#pragma unroll 1
    for (int k0 = 0; k0 < 256; k0 += 16) {
        __syncthreads();
        NN_LOAD(k0 + 8);
        MT_COMPUTE(0);
        MT_STORE(1);
        __syncthreads();
        bool more = (k0 + 16) < 256;
        if (more) NN_LOAD(k0 + 16);
        MT_COMPUTE(1);
        if (more) MT_STORE(0);
    }
#undef NN_LOAD

    float* on = Out + (size_t)n * CS;
    int c0 = col0 + tx * 4;
    if (MODE == 0) {
        const float* e1 = E1 + (size_t)n * CS;   // t3
#pragma unroll
        for (int i = 0; i < 8; ++i) {
            size_t idx = (size_t)(m0 + ty * 8 + i) * SS + c0;
            float4 e = *(const float4*)&e1[idx];
            *(float4*)&on[idx] = make_float4(e.x - acc[i][0], e.y - acc[i][1],
                                             e.z - acc[i][2], e.w - acc[i][3]);
        }
    } else {
        const float* e1 = E1 + (size_t)n * CS;   // t7
        const float* e2 = E2 + (size_t)n * CS;   // t17
        const float sc = 0.0625f;                // 1/sqrt(256)
#pragma unroll
        for (int i = 0; i < 8; ++i) {
            size_t idx = (size_t)(m0 + ty * 8 + i) * SS + c0;
            float4 a7 = *(const float4*)&e1[idx];
            float4 a17 = *(const float4*)&e2[idx];
            float4 r;
            r.x = fmaf(sc, acc[i][0], a7.x * a17.x);
            r.y = fmaf(sc, acc[i][1], a7.y * a17.y);
            r.z = fmaf(sc, acc[i][2], a7.z * a17.z);
            r.w = fmaf(sc, acc[i][3], a7.w * a17.w);
            *(float4*)&on[idx] = r;
        }
    }
}

// ---------------- small NN GEMM 64x64/4x4: t19 = s_hw * Amat @ t8 (natural store) ----------------
__global__ void __launch_bounds__(256) gemmT19(const float* __restrict__ A,
                                               const float* __restrict__ B,
                                               float* __restrict__ Out) {
    __shared__ float As[16][68];
    __shared__ float Bs[16][64];
    int n = blockIdx.z;
    int m0 = blockIdx.y * 64;
    int col0 = blockIdx.x * 64;
    const float* An = A + (size_t)n * 65536;
    const float* Bn = B + (size_t)n * 65536;
    int t = threadIdx.x;
    int tx = t & 15, ty = t >> 4;
    int am = t >> 2;
    int akq = (t & 3) * 4;
    int bp = t & 63;
    int bk = t >> 6;
    float acc[4][4] = {};
    for (int k0 = 0; k0 < 256; k0 += 16) {
        float4 a = *(const float4*)&An[(size_t)(m0 + am) * 256 + k0 + akq];
        float bv[4];
#pragma unroll
        for (int ps = 0; ps < 4; ++ps)
            bv[ps] = Bn[(size_t)(k0 + bk + 4 * ps) * 256 + col0 + bp];
        __syncthreads();
        As[akq + 0][am] = a.x;
        As[akq + 1][am] = a.y;
        As[akq + 2][am] = a.z;
        As[akq + 3][am] = a.w;
#pragma unroll
        for (int ps = 0; ps < 4; ++ps) Bs[bk + 4 * ps][bp] = bv[ps];
        __syncthreads();
#pragma unroll
        for (int kk = 0; kk < 16; ++kk) {
            float av[4], bw[4];
            *(float4*)av = *(const float4*)&As[kk][ty * 4];
            *(float4*)bw = *(const float4*)&Bs[kk][tx * 4];
#pragma unroll
            for (int i = 0; i < 4; ++i)
#pragma unroll
                for (int j = 0; j < 4; ++j) acc[i][j] = fmaf(av[i], bw[j], acc[i][j]);
        }
    }
    float* on = Out + (size_t)n * 65536;
    const float shw = 1.f / 56.f;
#pragma unroll
    for (int i = 0; i < 4; ++i)
        *(float4*)&on[(size_t)(m0 + ty * 4 + i) * 256 + col0 + tx * 4] =
            make_float4(acc[i][0] * shw, acc[i][1] * shw,
                        acc[i][2] * shw, acc[i][3] * shw);
}

// ---------------- NT GEMM: C[m,n] = scale * sum_k A[m,k]*B[n,k], M=N=256, K=3136 ----------------
__global__ void __launch_bounds__(256) gemmNT(const float* __restrict__ A,
                                              const float* __restrict__ B,
                                              float* __restrict__ Out,
                                              size_t strA, size_t strB, float scale) {
    __shared__ float As[16][68];
    __shared__ float Bs[16][68];
    int n = blockIdx.z;
    const float* An = A + (size_t)n * strA;
    const float* Bn = B + (size_t)n * strB;
    float* On = Out + (size_t)n * 65536;
    int m0 = blockIdx.y * 64, n0 = blockIdx.x * 64;
    int t = threadIdx.x;
    int tx = t & 15, ty = t >> 4;
    int r = t >> 2;
    int kq = (t & 3) * 4;
    float acc[4][4] = {};
    for (int k0 = 0; k0 < SS; k0 += 16) {
        float4 a = *(const float4*)&An[(size_t)(m0 + r) * SS + k0 + kq];
        float4 b = *(const float4*)&Bn[(size_t)(n0 + r) * SS + k0 + kq];
        __syncthreads();
        As[kq + 0][r] = a.x; As[kq + 1][r] = a.y; As[kq + 2][r] = a.z; As[kq + 3][r] = a.w;
        Bs[kq + 0][r] = b.x; Bs[kq + 1][r] = b.y; Bs[kq + 2][r] = b.z; Bs[kq + 3][r] = b.w;
        __syncthreads();
#pragma unroll
        for (int kk = 0; kk < 16; ++kk) {
            float av[4], bw[4];
            *(float4*)av = *(const float4*)&As[kk][ty * 4];
            *(float4*)bw = *(const float4*)&Bs[kk][tx * 4];
#pragma unroll
            for (int i = 0; i < 4; ++i)
#pragma unroll
                for (int j = 0; j < 4; ++j) acc[i][j] = fmaf(av[i], bw[j], acc[i][j]);
        }
    }
#pragma unroll
    for (int i = 0; i < 4; ++i) {
        float4 rr = make_float4(acc[i][0] * scale, acc[i][1] * scale,
                                acc[i][2] * scale, acc[i][3] * scale);
        *(float4*)&On[(size_t)(m0 + ty * 4 + i) * 256 + n0 + tx * 4] = rr;
    }
}

// ---------------- t11[n,s] = sum_c t3[n,c,s]*veff[c,s] ----------------
__global__ void calcT11() {
    int idx = blockIdx.x * 256 + threadIdx.x;   // n*SS + s
    int n = idx / SS;
    int s = idx - n * SS;
    const float* t3n = g_t3 + (size_t)n * CS + s;
    const float* vf = g_veff + s;
    float acc = 0.f;
#pragma unroll 8
    for (int c = 0; c < CC; ++c)
        acc = fmaf(t3n[(size_t)c * SS], vf[(size_t)c * SS], acc);
    g_t11[idx] = acc;
}

// ---------------- t13 = t11 - dwconv3x1_d2(max(t5,t7)) ----------------
__global__ void calcT13(const float* __restrict__ w12) {
    int idx = blockIdx.x * 256 + threadIdx.x;   // n*CC*SS + c*SS + p
    int p = idx % SS;
    int nc = idx / SS;
    int c = nc & 255;
    int n = nc >> 8;
    int h = p / 56, w = p - h * 56;
    float acc = 0.f;
#pragma unroll
    for (int r = 0; r < 3; ++r) {
        int hh = h + 2 * r - 2;
        if ((unsigned)hh < 56u) {
            size_t q = (size_t)nc * SS + hh * 56 + w;
            acc = fmaf(w12[c * 3 + r], fmaxf(g_t5[q], g_t7[q]), acc);
        }
    }
    g_t13[idx] = g_t11[(size_t)n * SS + p] - acc;
}

// ---------------- launch ----------------
extern "C" void kernel_launch(void* const* d_in, const int* in_sizes, int n_in,
                              void* d_out, int out_size) {
    const float* x   = (const float*)d_in[0];
    const float* p2  = (const float*)d_in[1];
    const float* w6  = (const float*)d_in[2];
    const float* w7  = (const float*)d_in[3];
    const float* p9  = (const float*)d_in[4];
    const float* p11 = (const float*)d_in[5];
    const float* w12 = (const float*)d_in[6];
    const float* w15 = (const float*)d_in[7];
    const float* p16 = (const float*)d_in[8];
    float* out = (float*)d_out;

    void *t3p, *t5p, *t7p, *t17p, *t13p, *t8p, *Amatp, *t19p, *w15tp;
    cudaGetSymbolAddress(&t3p, g_t3);
    cudaGetSymbolAddress(&t5p, g_t5);
    cudaGetSymbolAddress(&t7p, g_t7);
    cudaGetSymbolAddress(&t17p, g_t17);
    cudaGetSymbolAddress(&t13p, g_t13);
    cudaGetSymbolAddress(&t8p, g_t8);
    cudaGetSymbolAddress(&Amatp, g_Amat);
    cudaGetSymbolAddress(&t19p, g_t19);
    cudaGetSymbolAddress(&w15tp, g_w15t);

    // stage A: t3, t5
    stageA<<<NB * CC, 256>>>(x, p2);
    // weight prep (independent)
    prepW7<<<9 * CC, 256>>>(w7);
    prepW15T<<<CC, 256>>>(w15);
    prepVeff<<<SS, 256>>>(w6, p9, p11);
    // t7: big implicit-GEMM conv
    convT7k<<<dim3(49, 2, NB), 256>>>(x);
    // t17 = t3 - w15 @ roll(x, +1, h)
    gemmBig<0><<<dim3(49, 2, NB), 256>>>((const float*)w15tp, x, (float*)t17p,
                                         (const float*)t3p, nullptr, 0, (size_t)CS);
    // t8 = s_hw * t5 @ t3^T
    gemmNT<<<dim3(4, 4, NB), 256>>>((const float*)t5p, (const float*)t3p, (float*)t8p,
                                    (size_t)CS, (size_t)CS, 1.f / 56.f);
    // t11, t13
    calcT11<<<(NB * SS) / 256, 256>>>();
    calcT13<<<NCS / 256, 256>>>(w12);
    // Amat = t17 @ p16^T
    gemmNT<<<dim3(4, 4, NB), 256>>>((const float*)t17p, p16, (float*)Amatp,
                                    (size_t)CS, 0, 1.f);
    // t19 = s_hw * Amat @ t8 (natural layout = k-major A for the final GEMM)
    gemmT19<<<dim3(4, 4, NB), 256>>>((const float*)Amatp, (const float*)t8p,
                                     (float*)t19p);
    // out = s_c * t19(k-major) @ t13 + t7 * t17
    gemmBig<1><<<dim3(49, 2, NB), 256>>>((const float*)t19p, (const float*)t13p, out,
                                         (const float*)t7p, (const float*)t17p,
                                         (size_t)65536, (size_t)CS);
}

// round 6
// speedup vs baseline: 1.8917x; 1.5432x over previous
#include <cuda_runtime.h>
#include <math.h>

#define NB 8
#define CC 256
#define HHH 56
#define WWW 56
#define SS 3136
#define CS 802816      // CC*SS
#define NCS 6422528    // NB*CC*SS

// ---------------- scratch (static device globals; no runtime alloc) ----------------
__device__ float g_t3[NCS];
__device__ float g_t5[NCS];
__device__ float g_t7[NCS];
__device__ float g_t17[NCS];
__device__ float g_t13[NCS];
__device__ float g_t8[NB * CC * CC];
__device__ float g_Amat[NB * CC * CC];
__device__ float g_t19[NB * CC * CC];
__device__ float g_w7t[9 * CC * CC];      // [tap*256 + c][o]  (k-major)
__device__ float g_w15t[CC * CC];         // [c][o]            (k-major)
__device__ float g_veff[CS];              // [c][s]
__device__ float g_t11[NB * SS];

__device__ __forceinline__ float to_tf32(float v) {
    unsigned r;
    asm("cvt.rna.tf32.f32 %0, %1;" : "=r"(r) : "f"(v));
    return __uint_as_float(r);
}

// ---------------- stage A: t3 = (p2*x)^2 ; t5 = softmax_h(roll(t3,1,-1)) ----------------
__global__ void __launch_bounds__(256) stageA(const float* __restrict__ x,
                                              const float* __restrict__ p2) {
    int plane = blockIdx.x;            // n*256 + c
    int c = plane & 255;
    const float* xp = x + (size_t)plane * SS;
    const float* pp = p2 + (size_t)c * SS;
    float* t3p = g_t3 + (size_t)plane * SS;
    float* t5p = g_t5 + (size_t)plane * SS;
    __shared__ float sm[SS];
    for (int i = threadIdx.x; i < SS; i += 256) {
        float v = pp[i] * xp[i];
        v *= v;
        sm[i] = v;
        t3p[i] = v;
    }
    __syncthreads();
    int wc = threadIdx.x;              // source column
    if (wc < WWW) {
        float mx = -1e30f;
        for (int h = 0; h < HHH; ++h) mx = fmaxf(mx, sm[h * WWW + wc]);
        float s = 0.f;
        for (int h = 0; h < HHH; ++h) {
            float e = __expf(sm[h * WWW + wc] - mx);
            sm[h * WWW + wc] = e;
            s += e;
        }
        float inv = 1.f / s;
        int wout = (wc + WWW - 1) % WWW;
        for (int h = 0; h < HHH; ++h) {
            int ho = h + 1; if (ho == HHH) ho = 0;
            t5p[ho * WWW + wout] = sm[h * WWW + wc] * inv;
        }
    }
}

// ---------------- prep: transpose w7 (C,9C) -> w7t[tap*256+c][o] ----------------
__global__ void prepW7(const float* __restrict__ w7) {
    int idx = blockIdx.x * 256 + threadIdx.x;     // over 9*256*256
    int o = idx & 255;
    int k = idx >> 8;                              // tap*256 + c
    int tap = k >> 8;
    int cc = k & 255;
    g_w7t[idx] = w7[o * 2304 + cc * 9 + tap];
}

// ---------------- prep: w15t[c][o] = w15[o][c] ----------------
__global__ void prepW15T(const float* __restrict__ w15) {
    int idx = blockIdx.x * 256 + threadIdx.x;   // c*256 + o
    int o = idx & 255;
    int c = idx >> 8;
    g_w15t[idx] = w15[o * 256 + c];
}

// ---------------- prep: veff[c,s] = sum_o w6[o,c]*p9[o,s]*p11[o] ----------------
__global__ void prepVeff(const float* __restrict__ w6, const float* __restrict__ p9,
                         const float* __restrict__ p11) {
    int idx = blockIdx.x * 256 + threadIdx.x;     // c*SS + s
    int s = idx % SS;
    int c = idx / SS;
    float acc = 0.f;
#pragma unroll
    for (int o = 0; o < 32; ++o)
        acc = fmaf(w6[o * CC + c], p9[o * SS + s] * p11[o], acc);
    g_veff[idx] = acc;
}

// ================== convT7 via tf32 mma.sync: M=256, N=3136, K=2304 ==================
// CTA 128x128, 8 warps (2 M x 4 N), warp tile 64x32 = 4x4 m16n8k8 tiles.
// smem stride 136 -> frag-load bank map ti*8+g is a bijection (conflict-free).
__global__ void __launch_bounds__(256) convT7mma(const float* __restrict__ x) {
    __shared__ float As[2][16][136];
    __shared__ float Bs[2][16][136];
    int n = blockIdx.z;
    int m0 = blockIdx.y * 128;
    int col0 = blockIdx.x * 128;       // 25 tiles; last partial
    int t = threadIdx.x;
    int lane = t & 31, wid = t >> 5;
    int warp_m = wid & 1, warp_n = wid >> 1;
    int g = lane >> 2, ti = lane & 3;

    // A loader: rows ak, ak+8; cols am4..am4+3 (float4)
    int ak = t >> 5;
    int am4 = (t & 31) * 4;
    // B loader: pixel bp, rows kb..kb+7
    int bp = t & 127, kb = (t >> 7) * 8;
    int pglob = col0 + bp;
    bool pin = pglob < SS;
    int h = pin ? pglob / 56 : 0;
    int w = pin ? pglob - h * 56 : 0;
    const float* xn = x + (size_t)n * CS;

    float4 a0r, a1r;
    float br[8];
    float acc[4][4][4] = {};

#define CONV_LOAD(kg) {                                                        \
    int tap = (kg) >> 8; int kin = (kg) & 255;                                 \
    a0r = *(const float4*)&g_w7t[(size_t)((kg) + ak) * 256 + m0 + am4];        \
    a1r = *(const float4*)&g_w7t[(size_t)((kg) + ak + 8) * 256 + m0 + am4];    \
    int dy = (tap / 3) * 3 - 3, dxx = (tap % 3) * 3 - 3;                       \
    int hh = h + dy, ww = w + dxx;                                             \
    bool valid = pin && ((unsigned)hh < 56u) && ((unsigned)ww < 56u);          \
    int poff = hh * 56 + ww;                                                   \
    _Pragma("unroll")                                                          \
    for (int i = 0; i < 8; ++i)                                                \
        br[i] = valid ? xn[(size_t)(kin + kb + i) * SS + poff] : 0.f; }

#define CONV_STORE(buf) {                                                      \
    As[buf][ak][am4 + 0] = to_tf32(a0r.x);                                     \
    As[buf][ak][am4 + 1] = to_tf32(a0r.y);                                     \
    As[buf][ak][am4 + 2] = to_tf32(a0r.z);                                     \
    As[buf][ak][am4 + 3] = to_tf32(a0r.w);                                     \
    As[buf][ak + 8][am4 + 0] = to_tf32(a1r.x);                                 \
    As[buf][ak + 8][am4 + 1] = to_tf32(a1r.y);                                 \
    As[buf][ak + 8][am4 + 2] = to_tf32(a1r.z);                                 \
    As[buf][ak + 8][am4 + 3] = to_tf32(a1r.w);                                 \
    _Pragma("unroll")                                                          \
    for (int i = 0; i < 8; ++i) Bs[buf][kb + i][bp] = to_tf32(br[i]); }

#define MMA_STEP(buf, ks) {                                                    \
    unsigned bfr[4][2];                                                        \
    _Pragma("unroll")                                                          \
    for (int ni = 0; ni < 4; ++ni) {                                           \
        int nb = warp_n * 32 + ni * 8 + g;                                     \
        bfr[ni][0] = __float_as_uint(Bs[buf][(ks) + ti][nb]);                  \
        bfr[ni][1] = __float_as_uint(Bs[buf][(ks) + ti + 4][nb]);              \
    }                                                                          \
    _Pragma("unroll")                                                          \
    for (int mi = 0; mi < 4; ++mi) {                                           \
        unsigned afr[4];                                                       \
        int mb = warp_m * 64 + mi * 16 + g;                                    \
        afr[0] = __float_as_uint(As[buf][(ks) + ti][mb]);                      \
        afr[1] = __float_as_uint(As[buf][(ks) + ti][mb + 8]);                  \
        afr[2] = __float_as_uint(As[buf][(ks) + ti + 4][mb]);                  \
        afr[3] = __float_as_uint(As[buf][(ks) + ti + 4][mb + 8]);              \
        _Pragma("unroll")                                                      \
        for (int ni = 0; ni < 4; ++ni)                                         \
            asm volatile(                                                      \
                "mma.sync.aligned.m16n8k8.row.col.f32.tf32.tf32.f32 "          \
                "{%0,%1,%2,%3},{%4,%5,%6,%7},{%8,%9},{%0,%1,%2,%3};"           \
                : "+f"(acc[mi][ni][0]), "+f"(acc[mi][ni][1]),                  \
                  "+f"(acc[mi][ni][2]), "+f"(acc[mi][ni][3])                   \
                : "r"(afr[0]), "r"(afr[1]), "r"(afr[2]), "r"(afr[3]),          \
                  "r"(bfr[ni][0]), "r"(bfr[ni][1]));                           \
    } }

    CONV_LOAD(0);
    CONV_STORE(0);
#pragma unroll 1
    for (int kg = 0; kg < 2304; kg += 32) {
        __syncthreads();
        CONV_LOAD(kg + 16);
        MMA_STEP(0, 0);
        MMA_STEP(0, 8);
        CONV_STORE(1);
        __syncthreads();
        bool more = (kg + 32) < 2304;
        if (more) CONV_LOAD(kg + 32);
        MMA_STEP(1, 0);
        MMA_STEP(1, 8);
        if (more) CONV_STORE(0);
    }
#undef CONV_LOAD
#undef CONV_STORE
#undef MMA_STEP

    float* t7n = g_t7 + (size_t)n * CS;
#pragma unroll
    for (int mi = 0; mi < 4; ++mi) {
#pragma unroll
        for (int ni = 0; ni < 4; ++ni) {
            int row = m0 + warp_m * 64 + mi * 16 + g;
            int col = col0 + warp_n * 32 + ni * 8 + 2 * ti;
            if (col < SS) {
                *(float2*)&t7n[(size_t)row * SS + col] =
                    make_float2(acc[mi][ni][0], acc[mi][ni][1]);
                *(float2*)&t7n[(size_t)(row + 8) * SS + col] =
                    make_float2(acc[mi][ni][2], acc[mi][ni][3]);
            }
        }
    }
}

// ================== 128x64 tile / 8x4 microtile machinery (fp32 SIMT) ==================
#define MT_COMPUTE(buf)                                                       \
    _Pragma("unroll")                                                         \
    for (int kk = 0; kk < 8; ++kk) {                                          \
        float av[8], bv[4];                                                   \
        *(float4*)&av[0] = *(const float4*)&As[buf][kk][ty * 8];              \
        *(float4*)&av[4] = *(const float4*)&As[buf][kk][ty * 8 + 4];          \
        *(float4*)&bv[0] = *(const float4*)&Bs[buf][kk][tx * 4];              \
        _Pragma("unroll")                                                     \
        for (int i = 0; i < 8; ++i)                                           \
            _Pragma("unroll")                                                 \
            for (int j = 0; j < 4; ++j)                                       \
                acc[i][j] = fmaf(av[i], bv[j], acc[i][j]);                    \
    }

#define MT_STORE(buf) {                                                       \
    *(float4*)&As[buf][ak][am4] = a_reg;                                      \
    Bs[buf][kb + 0][bp] = b_reg[0];                                           \
    Bs[buf][kb + 1][bp] = b_reg[1]; }

// ---------------- NN GEMM, A k-major [256][256], N=3136, 128x64 tiles ----------------
// MODE 0: A=w15t, B = x rolled(+1,h); out t17 = t3 - acc
// MODE 1: A=t19 (k-major), B = t13; out = s_c*acc + t7*t17 -> final output
template <int MODE>
__global__ void __launch_bounds__(256) gemmBig(const float* __restrict__ A,
                                               const float* __restrict__ B,
                                               float* __restrict__ Out,
                                               const float* __restrict__ E1,
                                               const float* __restrict__ E2,
                                               size_t strA, size_t strB) {
    __shared__ float As[2][8][128];
    __shared__ float Bs[2][8][64];
    int n = blockIdx.z;
    int m0 = blockIdx.y * 128;
    int col0 = blockIdx.x * 64;
    const float* An = A + (size_t)n * strA;
    const float* Bn = B + (size_t)n * strB;
    int t = threadIdx.x;
    int tx = t & 15, ty = t >> 4;
    int ak = t >> 5, am4 = (t & 31) * 4;
    int bp = t & 63, kb = (t >> 6) * 2;
    int pglob = col0 + bp;
    int poff;
    if (MODE == 0) {
        int hh = pglob / 56, ww = pglob - hh * 56;
        int h2 = hh ? hh - 1 : 55;        // t14[h] = x[h-1 mod 56]
        poff = h2 * 56 + ww;
    } else {
        poff = pglob;
    }
    float4 a_reg; float b_reg[2];
    float acc[8][4] = {};

#define NN_LOAD(k0) {                                                         \
    a_reg = *(const float4*)&An[(size_t)((k0) + ak) * 256 + m0 + am4];        \
    b_reg[0] = Bn[(size_t)((k0) + kb + 0) * SS + poff];                       \
    b_reg[1] = Bn[(size_t)((k0) + kb + 1) * SS + poff]; }

    NN_LOAD(0);
    MT_STORE(0);
#pragma unroll 1
    for (int k0 = 0; k0 < 256; k0 += 16) {
        __syncthreads();
        NN_LOAD(k0 + 8);
        MT_COMPUTE(0);
        MT_STORE(1);
        __syncthreads();
        bool more = (k0 + 16) < 256;
        if (more) NN_LOAD(k0 + 16);
        MT_COMPUTE(1);
        if (more) MT_STORE(0);
    }
#undef NN_LOAD

    float* on = Out + (size_t)n * CS;
    int c0 = col0 + tx * 4;
    if (MODE == 0) {
        const float* e1 = E1 + (size_t)n * CS;   // t3
#pragma unroll
        for (int i = 0; i < 8; ++i) {
            size_t idx = (size_t)(m0 + ty * 8 + i) * SS + c0;
            float4 e = *(const float4*)&e1[idx];
            *(float4*)&on[idx] = make_float4(e.x - acc[i][0], e.y - acc[i][1],
                                             e.z - acc[i][2], e.w - acc[i][3]);
        }
    } else {
        const float* e1 = E1 + (size_t)n * CS;   // t7
        const float* e2 = E2 + (size_t)n * CS;   // t17
        const float sc = 0.0625f;                // 1/sqrt(256)
#pragma unroll
        for (int i = 0; i < 8; ++i) {
            size_t idx = (size_t)(m0 + ty * 8 + i) * SS + c0;
            float4 a7 = *(const float4*)&e1[idx];
            float4 a17 = *(const float4*)&e2[idx];
            float4 r;
            r.x = fmaf(sc, acc[i][0], a7.x * a17.x);
            r.y = fmaf(sc, acc[i][1], a7.y * a17.y);
            r.z = fmaf(sc, acc[i][2], a7.z * a17.z);
            r.w = fmaf(sc, acc[i][3], a7.w * a17.w);
            *(float4*)&on[idx] = r;
        }
    }
}

// ---------------- small NN GEMM 64x64/4x4: t19 = s_hw * Amat @ t8 (natural store) ----------------
__global__ void __launch_bounds__(256) gemmT19(const float* __restrict__ A,
                                               const float* __restrict__ B,
                                               float* __restrict__ Out) {
    __shared__ float As[16][68];
    __shared__ float Bs[16][64];
    int n = blockIdx.z;
    int m0 = blockIdx.y * 64;
    int col0 = blockIdx.x * 64;
    const float* An = A + (size_t)n * 65536;
    const float* Bn = B + (size_t)n * 65536;
    int t = threadIdx.x;
    int tx = t & 15, ty = t >> 4;
    int am = t >> 2;
    int akq = (t & 3) * 4;
    int bp = t & 63;
    int bk = t >> 6;
    float acc[4][4] = {};
    for (int k0 = 0; k0 < 256; k0 += 16) {
        float4 a = *(const float4*)&An[(size_t)(m0 + am) * 256 + k0 + akq];
        float bv[4];
#pragma unroll
        for (int ps = 0; ps < 4; ++ps)
            bv[ps] = Bn[(size_t)(k0 + bk + 4 * ps) * 256 + col0 + bp];
        __syncthreads();
        As[akq + 0][am] = a.x;
        As[akq + 1][am] = a.y;
        As[akq + 2][am] = a.z;
        As[akq + 3][am] = a.w;
#pragma unroll
        for (int ps = 0; ps < 4; ++ps) Bs[bk + 4 * ps][bp] = bv[ps];
        __syncthreads();
#pragma unroll
        for (int kk = 0; kk < 16; ++kk) {
            float av[4], bw[4];
            *(float4*)av = *(const float4*)&As[kk][ty * 4];
            *(float4*)bw = *(const float4*)&Bs[kk][tx * 4];
#pragma unroll
            for (int i = 0; i < 4; ++i)
#pragma unroll
                for (int j = 0; j < 4; ++j) acc[i][j] = fmaf(av[i], bw[j], acc[i][j]);
        }
    }
    float* on = Out + (size_t)n * 65536;
    const float shw = 1.f / 56.f;
#pragma unroll
    for (int i = 0; i < 4; ++i)
        *(float4*)&on[(size_t)(m0 + ty * 4 + i) * 256 + col0 + tx * 4] =
            make_float4(acc[i][0] * shw, acc[i][1] * shw,
                        acc[i][2] * shw, acc[i][3] * shw);
}

// ---------------- NT GEMM: C[m,n] = scale * sum_k A[m,k]*B[n,k], M=N=256, K=3136 ----------------
__global__ void __launch_bounds__(256) gemmNT(const float* __restrict__ A,
                                              const float* __restrict__ B,
                                              float* __restrict__ Out,
                                              size_t strA, size_t strB, float scale) {
    __shared__ float As[16][68];
    __shared__ float Bs[16][68];
    int n = blockIdx.z;
    const float* An = A + (size_t)n * strA;
    const float* Bn = B + (size_t)n * strB;
    float* On = Out + (size_t)n * 65536;
    int m0 = blockIdx.y * 64, n0 = blockIdx.x * 64;
    int t = threadIdx.x;
    int tx = t & 15, ty = t >> 4;
    int r = t >> 2;
    int kq = (t & 3) * 4;
    float acc[4][4] = {};
    for (int k0 = 0; k0 < SS; k0 += 16) {
        float4 a = *(const float4*)&An[(size_t)(m0 + r) * SS + k0 + kq];
        float4 b = *(const float4*)&Bn[(size_t)(n0 + r) * SS + k0 + kq];
        __syncthreads();
        As[kq + 0][r] = a.x; As[kq + 1][r] = a.y; As[kq + 2][r] = a.z; As[kq + 3][r] = a.w;
        Bs[kq + 0][r] = b.x; Bs[kq + 1][r] = b.y; Bs[kq + 2][r] = b.z; Bs[kq + 3][r] = b.w;
        __syncthreads();
#pragma unroll
        for (int kk = 0; kk < 16; ++kk) {
            float av[4], bw[4];
            *(float4*)av = *(const float4*)&As[kk][ty * 4];
            *(float4*)bw = *(const float4*)&Bs[kk][tx * 4];
#pragma unroll
            for (int i = 0; i < 4; ++i)
#pragma unroll
                for (int j = 0; j < 4; ++j) acc[i][j] = fmaf(av[i], bw[j], acc[i][j]);
        }
    }
#pragma unroll
    for (int i = 0; i < 4; ++i) {
        float4 rr = make_float4(acc[i][0] * scale, acc[i][1] * scale,
                                acc[i][2] * scale, acc[i][3] * scale);
        *(float4*)&On[(size_t)(m0 + ty * 4 + i) * 256 + n0 + tx * 4] = rr;
    }
}

// ---------------- t11[n,s] = sum_c t3[n,c,s]*veff[c,s] ----------------
__global__ void calcT11() {
    int idx = blockIdx.x * 256 + threadIdx.x;   // n*SS + s
    int n = idx / SS;
    int s = idx - n * SS;
    const float* t3n = g_t3 + (size_t)n * CS + s;
    const float* vf = g_veff + s;
    float acc = 0.f;
#pragma unroll 8
    for (int c = 0; c < CC; ++c)
        acc = fmaf(t3n[(size_t)c * SS], vf[(size_t)c * SS], acc);
    g_t11[idx] = acc;
}

// ---------------- t13 = t11 - dwconv3x1_d2(max(t5,t7)) ----------------
__global__ void calcT13(const float* __restrict__ w12) {
    int idx = blockIdx.x * 256 + threadIdx.x;   // n*CC*SS + c*SS + p
    int p = idx % SS;
    int nc = idx / SS;
    int c = nc & 255;
    int n = nc >> 8;
    int h = p / 56, w = p - h * 56;
    float acc = 0.f;
#pragma unroll
    for (int r = 0; r < 3; ++r) {
        int hh = h + 2 * r - 2;
        if ((unsigned)hh < 56u) {
            size_t q = (size_t)nc * SS + hh * 56 + w;
            acc = fmaf(w12[c * 3 + r], fmaxf(g_t5[q], g_t7[q]), acc);
        }
    }
    g_t13[idx] = g_t11[(size_t)n * SS + p] - acc;
}

// ---------------- launch ----------------
extern "C" void kernel_launch(void* const* d_in, const int* in_sizes, int n_in,
                              void* d_out, int out_size) {
    const float* x   = (const float*)d_in[0];
    const float* p2  = (const float*)d_in[1];
    const float* w6  = (const float*)d_in[2];
    const float* w7  = (const float*)d_in[3];
    const float* p9  = (const float*)d_in[4];
    const float* p11 = (const float*)d_in[5];
    const float* w12 = (const float*)d_in[6];
    const float* w15 = (const float*)d_in[7];
    const float* p16 = (const float*)d_in[8];
    float* out = (float*)d_out;

    void *t3p, *t5p, *t7p, *t17p, *t13p, *t8p, *Amatp, *t19p, *w15tp;
    cudaGetSymbolAddress(&t3p, g_t3);
    cudaGetSymbolAddress(&t5p, g_t5);
    cudaGetSymbolAddress(&t7p, g_t7);
    cudaGetSymbolAddress(&t17p, g_t17);
    cudaGetSymbolAddress(&t13p, g_t13);
    cudaGetSymbolAddress(&t8p, g_t8);
    cudaGetSymbolAddress(&Amatp, g_Amat);
    cudaGetSymbolAddress(&t19p, g_t19);
    cudaGetSymbolAddress(&w15tp, g_w15t);

    // stage A: t3, t5
    stageA<<<NB * CC, 256>>>(x, p2);
    // weight prep (independent)
    prepW7<<<9 * CC, 256>>>(w7);
    prepW15T<<<CC, 256>>>(w15);
    prepVeff<<<SS, 256>>>(w6, p9, p11);
    // t7: implicit-GEMM conv on tensor cores (tf32 mma.sync)
    convT7mma<<<dim3(25, 2, NB), 256>>>(x);
    // t17 = t3 - w15 @ roll(x, +1, h)
    gemmBig<0><<<dim3(49, 2, NB), 256>>>((const float*)w15tp, x, (float*)t17p,
                                         (const float*)t3p, nullptr, 0, (size_t)CS);
    // t8 = s_hw * t5 @ t3^T
    gemmNT<<<dim3(4, 4, NB), 256>>>((const float*)t5p, (const float*)t3p, (float*)t8p,
                                    (size_t)CS, (size_t)CS, 1.f / 56.f);
    // t11, t13
    calcT11<<<(NB * SS) / 256, 256>>>();
    calcT13<<<NCS / 256, 256>>>(w12);
    // Amat = t17 @ p16^T
    gemmNT<<<dim3(4, 4, NB), 256>>>((const float*)t17p, p16, (float*)Amatp,
                                    (size_t)CS, 0, 1.f);
    // t19 = s_hw * Amat @ t8 (natural layout = k-major A for the final GEMM)
    gemmT19<<<dim3(4, 4, NB), 256>>>((const float*)Amatp, (const float*)t8p,
                                     (float*)t19p);
    // out = s_c * t19(k-major) @ t13 + t7 * t17
    gemmBig<1><<<dim3(49, 2, NB), 256>>>((const float*)t19p, (const float*)t13p, out,
                                         (const float*)t7p, (const float*)t17p,
                                         (size_t)65536, (size_t)CS);
}

// round 7
// speedup vs baseline: 2.7271x; 1.4416x over previous
#include <cuda_runtime.h>
#include <math.h>

#define NB 8
#define CC 256
#define HHH 56
#define WWW 56
#define SS 3136
#define CS 802816      // CC*SS
#define NCS 6422528    // NB*CC*SS

// ---------------- scratch (static device globals; no runtime alloc) ----------------
__device__ float g_t3[NCS];
__device__ float g_t5[NCS];
__device__ float g_t7[NCS];
__device__ float g_t17[NCS];
__device__ float g_t13[NCS];
__device__ float g_t8[NB * CC * CC];
__device__ float g_Amat[NB * CC * CC];
__device__ float g_t19[NB * CC * CC];
__device__ float g_w7t[9 * CC * CC];      // [tap*256 + c][o]  (k-major)
__device__ float g_w15t[CC * CC];         // [c][o]            (k-major)
__device__ float g_veff[CS];              // [c][s]
__device__ float g_t11[NB * SS];
__device__ float g_part[4 * NB * CC * CC]; // split-K partials

__device__ __forceinline__ float to_tf32(float v) {
    unsigned r;
    asm("cvt.rna.tf32.f32 %0, %1;" : "=r"(r) : "f"(v));
    return __uint_as_float(r);
}

// Shared mma helper: one k8 step on 8-deep stage arrays ASL/BSL (float[8][136]).
// Needs in scope: warp_m, warp_n, g, ti, float acc[4][4][4].
#define MMA_K8(ASL, BSL) {                                                     \
    unsigned bfr[4][2];                                                        \
    _Pragma("unroll")                                                          \
    for (int ni = 0; ni < 4; ++ni) {                                           \
        int nb = warp_n * 32 + ni * 8 + g;                                     \
        bfr[ni][0] = __float_as_uint((BSL)[ti][nb]);                           \
        bfr[ni][1] = __float_as_uint((BSL)[ti + 4][nb]);                       \
    }                                                                          \
    _Pragma("unroll")                                                          \
    for (int mi = 0; mi < 4; ++mi) {                                           \
        unsigned afr[4];                                                       \
        int mb = warp_m * 64 + mi * 16 + g;                                    \
        afr[0] = __float_as_uint((ASL)[ti][mb]);                               \
        afr[1] = __float_as_uint((ASL)[ti][mb + 8]);                           \
        afr[2] = __float_as_uint((ASL)[ti + 4][mb]);                           \
        afr[3] = __float_as_uint((ASL)[ti + 4][mb + 8]);                       \
        _Pragma("unroll")                                                      \
        for (int ni = 0; ni < 4; ++ni)                                         \
            asm volatile(                                                      \
                "mma.sync.aligned.m16n8k8.row.col.f32.tf32.tf32.f32 "          \
                "{%0,%1,%2,%3},{%4,%5,%6,%7},{%8,%9},{%0,%1,%2,%3};"           \
                : "+f"(acc[mi][ni][0]), "+f"(acc[mi][ni][1]),                  \
                  "+f"(acc[mi][ni][2]), "+f"(acc[mi][ni][3])                   \
                : "r"(afr[0]), "r"(afr[1]), "r"(afr[2]), "r"(afr[3]),          \
                  "r"(bfr[ni][0]), "r"(bfr[ni][1]));                           \
    } }

// ---------------- stage A: t3 = (p2*x)^2 ; t5 = softmax_h(roll(t3,1,-1)) ----------------
__global__ void __launch_bounds__(256) stageA(const float* __restrict__ x,
                                              const float* __restrict__ p2) {
    int plane = blockIdx.x;            // n*256 + c
    int c = plane & 255;
    const float* xp = x + (size_t)plane * SS;
    const float* pp = p2 + (size_t)c * SS;
    float* t3p = g_t3 + (size_t)plane * SS;
    float* t5p = g_t5 + (size_t)plane * SS;
    __shared__ float sm[SS];
    for (int i = threadIdx.x; i < SS; i += 256) {
        float v = pp[i] * xp[i];
        v *= v;
        sm[i] = v;
        t3p[i] = v;
    }
    __syncthreads();
    int wc = threadIdx.x;              // source column
    if (wc < WWW) {
        float mx = -1e30f;
        for (int h = 0; h < HHH; ++h) mx = fmaxf(mx, sm[h * WWW + wc]);
        float s = 0.f;
        for (int h = 0; h < HHH; ++h) {
            float e = __expf(sm[h * WWW + wc] - mx);
            sm[h * WWW + wc] = e;
            s += e;
        }
        float inv = 1.f / s;
        int wout = (wc + WWW - 1) % WWW;
        for (int h = 0; h < HHH; ++h) {
            int ho = h + 1; if (ho == HHH) ho = 0;
            t5p[ho * WWW + wout] = sm[h * WWW + wc] * inv;
        }
    }
}

// ---------------- prep kernels ----------------
__global__ void prepW7(const float* __restrict__ w7) {
    int idx = blockIdx.x * 256 + threadIdx.x;     // over 9*256*256
    int o = idx & 255;
    int k = idx >> 8;                              // tap*256 + c
    int tap = k >> 8;
    int cc = k & 255;
    g_w7t[idx] = w7[o * 2304 + cc * 9 + tap];
}

__global__ void prepW15T(const float* __restrict__ w15) {
    int idx = blockIdx.x * 256 + threadIdx.x;   // c*256 + o
    int o = idx & 255;
    int c = idx >> 8;
    g_w15t[idx] = w15[o * 256 + c];
}

__global__ void prepVeff(const float* __restrict__ w6, const float* __restrict__ p9,
                         const float* __restrict__ p11) {
    int idx = blockIdx.x * 256 + threadIdx.x;     // c*SS + s
    int s = idx % SS;
    int c = idx / SS;
    float acc = 0.f;
#pragma unroll
    for (int o = 0; o < 32; ++o)
        acc = fmaf(w6[o * CC + c], p9[o * SS + s] * p11[o], acc);
    g_veff[idx] = acc;
}

// ================== convT7 via tf32 mma.sync: M=256, N=3136, K=2304 ==================
__global__ void __launch_bounds__(256) convT7mma(const float* __restrict__ x) {
    __shared__ float As[2][16][136];
    __shared__ float Bs[2][16][136];
    int n = blockIdx.z;
    int m0 = blockIdx.y * 128;
    int col0 = blockIdx.x * 128;       // 25 tiles; last partial
    int t = threadIdx.x;
    int lane = t & 31, wid = t >> 5;
    int warp_m = wid & 1, warp_n = wid >> 1;
    int g = lane >> 2, ti = lane & 3;

    int ak = t >> 5;
    int am4 = (t & 31) * 4;
    int bp = t & 127, kb = (t >> 7) * 8;
    int pglob = col0 + bp;
    bool pin = pglob < SS;
    int h = pin ? pglob / 56 : 0;
    int w = pin ? pglob - h * 56 : 0;
    const float* xn = x + (size_t)n * CS;

    float4 a0r, a1r;
    float br[8];
    float acc[4][4][4] = {};

#define CONV_LOAD(kg) {                                                        \
    int tap = (kg) >> 8; int kin = (kg) & 255;                                 \
    a0r = *(const float4*)&g_w7t[(size_t)((kg) + ak) * 256 + m0 + am4];        \
    a1r = *(const float4*)&g_w7t[(size_t)((kg) + ak + 8) * 256 + m0 + am4];    \
    int dy = (tap / 3) * 3 - 3, dxx = (tap % 3) * 3 - 3;                       \
    int hh = h + dy, ww = w + dxx;                                             \
    bool valid = pin && ((unsigned)hh < 56u) && ((unsigned)ww < 56u);          \
    int poff = hh * 56 + ww;                                                   \
    _Pragma("unroll")                                                          \
    for (int i = 0; i < 8; ++i)                                                \
        br[i] = valid ? xn[(size_t)(kin + kb + i) * SS + poff] : 0.f; }

#define CONV_STORE(buf) {                                                      \
    As[buf][ak][am4 + 0] = to_tf32(a0r.x);                                     \
    As[buf][ak][am4 + 1] = to_tf32(a0r.y);                                     \
    As[buf][ak][am4 + 2] = to_tf32(a0r.z);                                     \
    As[buf][ak][am4 + 3] = to_tf32(a0r.w);                                     \
    As[buf][ak + 8][am4 + 0] = to_tf32(a1r.x);                                 \
    As[buf][ak + 8][am4 + 1] = to_tf32(a1r.y);                                 \
    As[buf][ak + 8][am4 + 2] = to_tf32(a1r.z);                                 \
    As[buf][ak + 8][am4 + 3] = to_tf32(a1r.w);                                 \
    _Pragma("unroll")                                                          \
    for (int i = 0; i < 8; ++i) Bs[buf][kb + i][bp] = to_tf32(br[i]); }

#define MMA_STEP16(buf, ks) {                                                  \
    unsigned bfr[4][2];                                                        \
    _Pragma("unroll")                                                          \
    for (int ni = 0; ni < 4; ++ni) {                                           \
        int nb = warp_n * 32 + ni * 8 + g;                                     \
        bfr[ni][0] = __float_as_uint(Bs[buf][(ks) + ti][nb]);                  \
        bfr[ni][1] = __float_as_uint(Bs[buf][(ks) + ti + 4][nb]);              \
    }                                                                          \
    _Pragma("unroll")                                                          \
    for (int mi = 0; mi < 4; ++mi) {                                           \
        unsigned afr[4];                                                       \
        int mb = warp_m * 64 + mi * 16 + g;                                    \
        afr[0] = __float_as_uint(As[buf][(ks) + ti][mb]);                      \
        afr[1] = __float_as_uint(As[buf][(ks) + ti][mb + 8]);                  \
        afr[2] = __float_as_uint(As[buf][(ks) + ti + 4][mb]);                  \
        afr[3] = __float_as_uint(As[buf][(ks) + ti + 4][mb + 8]);              \
        _Pragma("unroll")                                                      \
        for (int ni = 0; ni < 4; ++ni)                                         \
            asm volatile(                                                      \
                "mma.sync.aligned.m16n8k8.row.col.f32.tf32.tf32.f32 "          \
                "{%0,%1,%2,%3},{%4,%5,%6,%7},{%8,%9},{%0,%1,%2,%3};"           \
                : "+f"(acc[mi][ni][0]), "+f"(acc[mi][ni][1]),                  \
                  "+f"(acc[mi][ni][2]), "+f"(acc[mi][ni][3])                   \
                : "r"(afr[0]), "r"(afr[1]), "r"(afr[2]), "r"(afr[3]),          \
                  "r"(bfr[ni][0]), "r"(bfr[ni][1]));                           \
    } }

    CONV_LOAD(0);
    CONV_STORE(0);
#pragma unroll 1
    for (int kg = 0; kg < 2304; kg += 32) {
        __syncthreads();
        CONV_LOAD(kg + 16);
        MMA_STEP16(0, 0);
        MMA_STEP16(0, 8);
        CONV_STORE(1);
        __syncthreads();
        bool more = (kg + 32) < 2304;
        if (more) CONV_LOAD(kg + 32);
        MMA_STEP16(1, 0);
        MMA_STEP16(1, 8);
        if (more) CONV_STORE(0);
    }
#undef CONV_LOAD
#undef CONV_STORE
#undef MMA_STEP16

    float* t7n = g_t7 + (size_t)n * CS;
#pragma unroll
    for (int mi = 0; mi < 4; ++mi) {
#pragma unroll
        for (int ni = 0; ni < 4; ++ni) {
            int row = m0 + warp_m * 64 + mi * 16 + g;
            int col = col0 + warp_n * 32 + ni * 8 + 2 * ti;
            if (col < SS) {
                *(float2*)&t7n[(size_t)row * SS + col] =
                    make_float2(acc[mi][ni][0], acc[mi][ni][1]);
                *(float2*)&t7n[(size_t)(row + 8) * SS + col] =
                    make_float2(acc[mi][ni][2], acc[mi][ni][3]);
            }
        }
    }
}

// ================== NT GEMM via mma + split-K: Part = A @ B^T (chunk) ==================
// M=N=256, K=3136 in 4 chunks of 784. grid (2, 2, NB*4). CTA tile 128x128.
__global__ void __launch_bounds__(256) gemmNTmma(const float* __restrict__ A,
                                                 const float* __restrict__ B,
                                                 float* __restrict__ Part,
                                                 size_t strA, size_t strB) {
    __shared__ float As[2][8][136];
    __shared__ float Bs[2][8][136];
    int z = blockIdx.z;
    int n = z >> 2, split = z & 3;
    int kbeg = split * 784;
    const float* An = A + (size_t)n * strA;
    const float* Bn = B + (size_t)n * strB;
    float* P = Part + (size_t)z * 65536;
    int m0 = blockIdx.y * 128, n0 = blockIdx.x * 128;
    int t = threadIdx.x;
    int lane = t & 31, wid = t >> 5;
    int warp_m = wid & 1, warp_n = wid >> 1;
    int g = lane >> 2, ti = lane & 3;
    int row = t & 127, kq = (t >> 7) * 4;
    float4 a_reg, b_reg;
    float acc[4][4][4] = {};

#define NT_LOAD(k0) {                                                          \
    a_reg = *(const float4*)&An[(size_t)(m0 + row) * SS + (k0) + kq];          \
    b_reg = *(const float4*)&Bn[(size_t)(n0 + row) * SS + (k0) + kq]; }

#define NT_STORE(buf) {                                                        \
    As[buf][kq + 0][row] = to_tf32(a_reg.x);                                   \
    As[buf][kq + 1][row] = to_tf32(a_reg.y);                                   \
    As[buf][kq + 2][row] = to_tf32(a_reg.z);                                   \
    As[buf][kq + 3][row] = to_tf32(a_reg.w);                                   \
    Bs[buf][kq + 0][row] = to_tf32(b_reg.x);                                   \
    Bs[buf][kq + 1][row] = to_tf32(b_reg.y);                                   \
    Bs[buf][kq + 2][row] = to_tf32(b_reg.z);                                   \
    Bs[buf][kq + 3][row] = to_tf32(b_reg.w); }

    NT_LOAD(kbeg);
    NT_STORE(0);
#pragma unroll 1
    for (int k0 = kbeg; k0 < kbeg + 784; k0 += 16) {
        __syncthreads();
        NT_LOAD(k0 + 8);
        MMA_K8(As[0], Bs[0]);
        NT_STORE(1);
        __syncthreads();
        bool more = (k0 + 16) < kbeg + 784;
        if (more) NT_LOAD(k0 + 16);
        MMA_K8(As[1], Bs[1]);
        if (more) NT_STORE(0);
    }
#undef NT_LOAD
#undef NT_STORE

#pragma unroll
    for (int mi = 0; mi < 4; ++mi) {
#pragma unroll
        for (int ni = 0; ni < 4; ++ni) {
            int r = m0 + warp_m * 64 + mi * 16 + g;
            int c = n0 + warp_n * 32 + ni * 8 + 2 * ti;
            *(float2*)&P[(size_t)r * 256 + c] =
                make_float2(acc[mi][ni][0], acc[mi][ni][1]);
            *(float2*)&P[(size_t)(r + 8) * 256 + c] =
                make_float2(acc[mi][ni][2], acc[mi][ni][3]);
        }
    }
}

// ---------------- reduce split-K partials ----------------
__global__ void ntReduce(const float* __restrict__ Part, float* __restrict__ Out,
                         float scale) {
    int idx = blockIdx.x * 256 + threadIdx.x;   // over NB*65536
    int nb = idx >> 16;
    int r = idx & 65535;
    float s = 0.f;
#pragma unroll
    for (int sp = 0; sp < 4; ++sp)
        s += Part[(size_t)(nb * 4 + sp) * 65536 + r];
    Out[idx] = s * scale;
}

// ================== final GEMM via mma: out = s_c * t19(k-major) @ t13 + t7*t17 ==================
// M=256, N=3136, K=256. grid (25, 2, NB).
__global__ void __launch_bounds__(256) gemmOutMma(const float* __restrict__ A,
                                                  const float* __restrict__ B,
                                                  float* __restrict__ Out,
                                                  const float* __restrict__ E1,
                                                  const float* __restrict__ E2) {
    __shared__ float As[2][8][136];
    __shared__ float Bs[2][8][136];
    int n = blockIdx.z;
    int m0 = blockIdx.y * 128;
    int col0 = blockIdx.x * 128;
    const float* An = A + (size_t)n * 65536;
    const float* Bn = B + (size_t)n * CS;
    int t = threadIdx.x;
    int lane = t & 31, wid = t >> 5;
    int warp_m = wid & 1, warp_n = wid >> 1;
    int g = lane >> 2, ti = lane & 3;
    int ak = t >> 5, am4 = (t & 31) * 4;      // A: row ak (k), 4 m cols
    int bp = t & 127, kb = (t >> 7) * 4;      // B: pixel bp, k rows kb..kb+3
    int pglob = col0 + bp;
    bool pin = pglob < SS;
    int poff = pin ? pglob : 0;
    float4 a_reg; float br[4];
    float acc[4][4][4] = {};

#define FN_LOAD(k0) {                                                          \
    a_reg = *(const float4*)&An[(size_t)((k0) + ak) * 256 + m0 + am4];         \
    _Pragma("unroll")                                                          \
    for (int i = 0; i < 4; ++i)                                                \
        br[i] = pin ? Bn[(size_t)((k0) + kb + i) * SS + poff] : 0.f; }

#define FN_STORE(buf) {                                                        \
    As[buf][ak][am4 + 0] = to_tf32(a_reg.x);                                   \
    As[buf][ak][am4 + 1] = to_tf32(a_reg.y);                                   \
    As[buf][ak][am4 + 2] = to_tf32(a_reg.z);                                   \
    As[buf][ak][am4 + 3] = to_tf32(a_reg.w);                                   \
    _Pragma("unroll")                                                          \
    for (int i = 0; i < 4; ++i) Bs[buf][kb + i][bp] = to_tf32(br[i]); }

    FN_LOAD(0);
    FN_STORE(0);
#pragma unroll 1
    for (int k0 = 0; k0 < 256; k0 += 16) {
        __syncthreads();
        FN_LOAD(k0 + 8);
        MMA_K8(As[0], Bs[0]);
        FN_STORE(1);
        __syncthreads();
        bool more = (k0 + 16) < 256;
        if (more) FN_LOAD(k0 + 16);
        MMA_K8(As[1], Bs[1]);
        if (more) FN_STORE(0);
    }
#undef FN_LOAD
#undef FN_STORE

    float* on = Out + (size_t)n * CS;
    const float* e1 = E1 + (size_t)n * CS;   // t7
    const float* e2 = E2 + (size_t)n * CS;   // t17
    const float sc = 0.0625f;                // 1/sqrt(256)
#pragma unroll
    for (int mi = 0; mi < 4; ++mi) {
#pragma unroll
        for (int ni = 0; ni < 4; ++ni) {
            int row = m0 + warp_m * 64 + mi * 16 + g;
            int col = col0 + warp_n * 32 + ni * 8 + 2 * ti;
            if (col < SS) {
                size_t i0 = (size_t)row * SS + col;
                size_t i1 = (size_t)(row + 8) * SS + col;
                float2 a7 = *(const float2*)&e1[i0];
                float2 a17 = *(const float2*)&e2[i0];
                float2 r0;
                r0.x = fmaf(sc, acc[mi][ni][0], a7.x * a17.x);
                r0.y = fmaf(sc, acc[mi][ni][1], a7.y * a17.y);
                *(float2*)&on[i0] = r0;
                float2 b7 = *(const float2*)&e1[i1];
                float2 b17 = *(const float2*)&e2[i1];
                float2 r1;
                r1.x = fmaf(sc, acc[mi][ni][2], b7.x * b17.x);
                r1.y = fmaf(sc, acc[mi][ni][3], b7.y * b17.y);
                *(float2*)&on[i1] = r1;
            }
        }
    }
}

// ================== fp32 SIMT 128x64/8x4 engine (kept for mode0: t17 exact) ==================
#define MT_COMPUTE(buf)                                                       \
    _Pragma("unroll")                                                         \
    for (int kk = 0; kk < 8; ++kk) {                                          \
        float av[8], bv[4];                                                   \
        *(float4*)&av[0] = *(const float4*)&As[buf][kk][ty * 8];              \
        *(float4*)&av[4] = *(const float4*)&As[buf][kk][ty * 8 + 4];          \
        *(float4*)&bv[0] = *(const float4*)&Bs[buf][kk][tx * 4];              \
        _Pragma("unroll")                                                     \
        for (int i = 0; i < 8; ++i)                                           \
            _Pragma("unroll")                                                 \
            for (int j = 0; j < 4; ++j)                                       \
                acc[i][j] = fmaf(av[i], bv[j], acc[i][j]);                    \
    }

#define MT_STORE(buf) {                                                       \
    *(float4*)&As[buf][ak][am4] = a_reg;                                      \
    Bs[buf][kb + 0][bp] = b_reg[0];                                           \
    Bs[buf][kb + 1][bp] = b_reg[1]; }

// t17 = t3 - w15 @ roll(x,+1,h).  A=w15t k-major, B=x with rolled rows.
__global__ void __launch_bounds__(256) gemmT17(const float* __restrict__ A,
                                               const float* __restrict__ B,
                                               float* __restrict__ Out,
                                               const float* __restrict__ E1) {
    __shared__ float As[2][8][128];
    __shared__ float Bs[2][8][64];
    int n = blockIdx.z;
    int m0 = blockIdx.y * 128;
    int col0 = blockIdx.x * 64;
    const float* An = A;
    const float* Bn = B + (size_t)n * CS;
    int t = threadIdx.x;
    int tx = t & 15, ty = t >> 4;
    int ak = t >> 5, am4 = (t & 31) * 4;
    int bp = t & 63, kb = (t >> 6) * 2;
    int pglob = col0 + bp;
    int hh = pglob / 56, ww = pglob - hh * 56;
    int h2 = hh ? hh - 1 : 55;        // t14[h] = x[h-1 mod 56]
    int poff = h2 * 56 + ww;
    float4 a_reg; float b_reg[2];
    float acc[8][4] = {};

#define NN_LOAD(k0) {                                                         \
    a_reg = *(const float4*)&An[(size_t)((k0) + ak) * 256 + m0 + am4];        \
    b_reg[0] = Bn[(size_t)((k0) + kb + 0) * SS + poff];                       \
    b_reg[1] = Bn[(size_t)((k0) + kb + 1) * SS + poff]; }

    NN_LOAD(0);
    MT_STORE(0);
#pragma unroll 1
    for (int k0 = 0; k0 < 256; k0 += 16) {
        __syncthreads();
        NN_LOAD(k0 + 8);
        MT_COMPUTE(0);
        MT_STORE(1);
        __syncthreads();
        bool more = (k0 + 16) < 256;
        if (more) NN_LOAD(k0 + 16);
        MT_COMPUTE(1);
        if (more) MT_STORE(0);
    }
#undef NN_LOAD

    float* on = Out + (size_t)n * CS;
    const float* e1 = E1 + (size_t)n * CS;   // t3
    int c0 = col0 + tx * 4;
#pragma unroll
    for (int i = 0; i < 8; ++i) {
        size_t idx = (size_t)(m0 + ty * 8 + i) * SS + c0;
        float4 e = *(const float4*)&e1[idx];
        *(float4*)&on[idx] = make_float4(e.x - acc[i][0], e.y - acc[i][1],
                                         e.z - acc[i][2], e.w - acc[i][3]);
    }
}

// ---------------- small NN GEMM 64x64/4x4: t19 = s_hw * Amat @ t8 ----------------
__global__ void __launch_bounds__(256) gemmT19(const float* __restrict__ A,
                                               const float* __restrict__ B,
                                               float* __restrict__ Out) {
    __shared__ float As[16][68];
    __shared__ float Bs[16][64];
    int n = blockIdx.z;
    int m0 = blockIdx.y * 64;
    int col0 = blockIdx.x * 64;
    const float* An = A + (size_t)n * 65536;
    const float* Bn = B + (size_t)n * 65536;
    int t = threadIdx.x;
    int tx = t & 15, ty = t >> 4;
    int am = t >> 2;
    int akq = (t & 3) * 4;
    int bp = t & 63;
    int bk = t >> 6;
    float acc[4][4] = {};
    for (int k0 = 0; k0 < 256; k0 += 16) {
        float4 a = *(const float4*)&An[(size_t)(m0 + am) * 256 + k0 + akq];
        float bv[4];
#pragma unroll
        for (int ps = 0; ps < 4; ++ps)
            bv[ps] = Bn[(size_t)(k0 + bk + 4 * ps) * 256 + col0 + bp];
        __syncthreads();
        As[akq + 0][am] = a.x;
        As[akq + 1][am] = a.y;
        As[akq + 2][am] = a.z;
        As[akq + 3][am] = a.w;
#pragma unroll
        for (int ps = 0; ps < 4; ++ps) Bs[bk + 4 * ps][bp] = bv[ps];
        __syncthreads();
#pragma unroll
        for (int kk = 0; kk < 16; ++kk) {
            float av[4], bw[4];
            *(float4*)av = *(const float4*)&As[kk][ty * 4];
            *(float4*)bw = *(const float4*)&Bs[kk][tx * 4];
#pragma unroll
            for (int i = 0; i < 4; ++i)
#pragma unroll
                for (int j = 0; j < 4; ++j) acc[i][j] = fmaf(av[i], bw[j], acc[i][j]);
        }
    }
    float* on = Out + (size_t)n * 65536;
    const float shw = 1.f / 56.f;
#pragma unroll
    for (int i = 0; i < 4; ++i)
        *(float4*)&on[(size_t)(m0 + ty * 4 + i) * 256 + col0 + tx * 4] =
            make_float4(acc[i][0] * shw, acc[i][1] * shw,
                        acc[i][2] * shw, acc[i][3] * shw);
}

// ---------------- t11[n,s] = sum_c t3[n,c,s]*veff[c,s] ----------------
__global__ void calcT11() {
    int idx = blockIdx.x * 256 + threadIdx.x;   // n*SS + s
    int n = idx / SS;
    int s = idx - n * SS;
    const float* t3n = g_t3 + (size_t)n * CS + s;
    const float* vf = g_veff + s;
    float acc = 0.f;
#pragma unroll 8
    for (int c = 0; c < CC; ++c)
        acc = fmaf(t3n[(size_t)c * SS], vf[(size_t)c * SS], acc);
    g_t11[idx] = acc;
}

// ---------------- t13 = t11 - dwconv3x1_d2(max(t5,t7)) ----------------
__global__ void calcT13(const float* __restrict__ w12) {
    int idx = blockIdx.x * 256 + threadIdx.x;   // n*CC*SS + c*SS + p
    int p = idx % SS;
    int nc = idx / SS;
    int c = nc & 255;
    int n = nc >> 8;
    int h = p / 56, w = p - h * 56;
    float acc = 0.f;
#pragma unroll
    for (int r = 0; r < 3; ++r) {
        int hh = h + 2 * r - 2;
        if ((unsigned)hh < 56u) {
            size_t q = (size_t)nc * SS + hh * 56 + w;
            acc = fmaf(w12[c * 3 + r], fmaxf(g_t5[q], g_t7[q]), acc);
        }
    }
    g_t13[idx] = g_t11[(size_t)n * SS + p] - acc;
}

// ---------------- launch ----------------
extern "C" void kernel_launch(void* const* d_in, const int* in_sizes, int n_in,
                              void* d_out, int out_size) {
    const float* x   = (const float*)d_in[0];
    const float* p2  = (const float*)d_in[1];
    const float* w6  = (const float*)d_in[2];
    const float* w7  = (const float*)d_in[3];
    const float* p9  = (const float*)d_in[4];
    const float* p11 = (const float*)d_in[5];
    const float* w12 = (const float*)d_in[6];
    const float* w15 = (const float*)d_in[7];
    const float* p16 = (const float*)d_in[8];
    float* out = (float*)d_out;

    void *t3p, *t5p, *t7p, *t17p, *t13p, *t8p, *Amatp, *t19p, *w15tp, *partp;
    cudaGetSymbolAddress(&t3p, g_t3);
    cudaGetSymbolAddress(&t5p, g_t5);
    cudaGetSymbolAddress(&t7p, g_t7);
    cudaGetSymbolAddress(&t17p, g_t17);
    cudaGetSymbolAddress(&t13p, g_t13);
    cudaGetSymbolAddress(&t8p, g_t8);
    cudaGetSymbolAddress(&Amatp, g_Amat);
    cudaGetSymbolAddress(&t19p, g_t19);
    cudaGetSymbolAddress(&w15tp, g_w15t);
    cudaGetSymbolAddress(&partp, g_part);

    // stage A: t3, t5
    stageA<<<NB * CC, 256>>>(x, p2);
    // weight prep (independent)
    prepW7<<<9 * CC, 256>>>(w7);
    prepW15T<<<CC, 256>>>(w15);
    prepVeff<<<SS, 256>>>(w6, p9, p11);
    // t7: implicit-GEMM conv on tensor cores (tf32 mma.sync)
    convT7mma<<<dim3(25, 2, NB), 256>>>(x);
    // t17 = t3 - w15 @ roll(x, +1, h)   (exact fp32 — feeds 3 consumers)
    gemmT17<<<dim3(49, 2, NB), 256>>>((const float*)w15tp, x, (float*)t17p,
                                      (const float*)t3p);
    // t8 = s_hw * t5 @ t3^T  (tf32 mma, split-K 4 + reduce)
    gemmNTmma<<<dim3(2, 2, NB * 4), 256>>>((const float*)t5p, (const float*)t3p,
                                           (float*)partp, (size_t)CS, (size_t)CS);
    ntReduce<<<NB * 256, 256>>>((const float*)partp, (float*)t8p, 1.f / 56.f);
    // t11, t13
    calcT11<<<(NB * SS) / 256, 256>>>();
    calcT13<<<NCS / 256, 256>>>(w12);
    // Amat = t17 @ p16^T  (tf32 mma, split-K 4 + reduce)
    gemmNTmma<<<dim3(2, 2, NB * 4), 256>>>((const float*)t17p, p16,
                                           (float*)partp, (size_t)CS, (size_t)0);
    ntReduce<<<NB * 256, 256>>>((const float*)partp, (float*)Amatp, 1.f);
    // t19 = s_hw * Amat @ t8 (natural layout = k-major A for the final GEMM)
    gemmT19<<<dim3(4, 4, NB), 256>>>((const float*)Amatp, (const float*)t8p,
                                     (float*)t19p);
    // out = s_c * t19(k-major) @ t13 + t7 * t17  (tf32 mma, fused epilogue)
    gemmOutMma<<<dim3(25, 2, NB), 256>>>((const float*)t19p, (const float*)t13p, out,
                                         (const float*)t7p, (const float*)t17p);
}

// round 8
// speedup vs baseline: 2.9782x; 1.0921x over previous
#include <cuda_runtime.h>
#include <math.h>

#define NB 8
#define CC 256
#define HHH 56
#define WWW 56
#define SS 3136
#define CS 802816      // CC*SS
#define NCS 6422528    // NB*CC*SS

// ---------------- scratch (static device globals; no runtime alloc) ----------------
__device__ float g_t3[NCS];
__device__ float g_t5[NCS];
__device__ float g_t7[NCS];
__device__ float g_t17[NCS];
__device__ float g_t13[NCS];
__device__ float g_t8[NB * CC * CC];
__device__ float g_Amat[NB * CC * CC];
__device__ float g_t19[NB * CC * CC];
__device__ float g_w7t[9 * CC * CC];      // [tap*256 + c][o]  (k-major, PRE-tf32)
__device__ float g_w15t[CC * CC];         // [c][o]            (k-major, PRE-tf32)
__device__ float g_veff[CS];              // [c][s]
__device__ float g_t11[NB * SS];
__device__ float g_part[4 * NB * CC * CC]; // split-K partials

__device__ __forceinline__ float to_tf32(float v) {
    unsigned r;
    asm("cvt.rna.tf32.f32 %0, %1;" : "=r"(r) : "f"(v));
    return __uint_as_float(r);
}

// Shared mma helper: one k8 step on 8-deep stage arrays ASL/BSL (float[8][136]).
// Needs in scope: warp_m, warp_n, g, ti, float acc[4][4][4].
#define MMA_K8(ASL, BSL) {                                                     \
    unsigned bfr[4][2];                                                        \
    _Pragma("unroll")                                                          \
    for (int ni = 0; ni < 4; ++ni) {                                           \
        int nb = warp_n * 32 + ni * 8 + g;                                     \
        bfr[ni][0] = __float_as_uint((BSL)[ti][nb]);                           \
        bfr[ni][1] = __float_as_uint((BSL)[ti + 4][nb]);                       \
    }                                                                          \
    _Pragma("unroll")                                                          \
    for (int mi = 0; mi < 4; ++mi) {                                           \
        unsigned afr[4];                                                       \
        int mb = warp_m * 64 + mi * 16 + g;                                    \
        afr[0] = __float_as_uint((ASL)[ti][mb]);                               \
        afr[1] = __float_as_uint((ASL)[ti][mb + 8]);                           \
        afr[2] = __float_as_uint((ASL)[ti + 4][mb]);                           \
        afr[3] = __float_as_uint((ASL)[ti + 4][mb + 8]);                       \
        _Pragma("unroll")                                                      \
        for (int ni = 0; ni < 4; ++ni)                                         \
            asm volatile(                                                      \
                "mma.sync.aligned.m16n8k8.row.col.f32.tf32.tf32.f32 "          \
                "{%0,%1,%2,%3},{%4,%5,%6,%7},{%8,%9},{%0,%1,%2,%3};"           \
                : "+f"(acc[mi][ni][0]), "+f"(acc[mi][ni][1]),                  \
                  "+f"(acc[mi][ni][2]), "+f"(acc[mi][ni][3])                   \
                : "r"(afr[0]), "r"(afr[1]), "r"(afr[2]), "r"(afr[3]),          \
                  "r"(bfr[ni][0]), "r"(bfr[ni][1]));                           \
    } }

// ---------------- stage A: t3 = (p2*x)^2 ; t5 = softmax_h(roll(t3,1,-1)) ----------------
__global__ void __launch_bounds__(256) stageA(const float* __restrict__ x,
                                              const float* __restrict__ p2) {
    int plane = blockIdx.x;            // n*256 + c
    int c = plane & 255;
    const float* xp = x + (size_t)plane * SS;
    const float* pp = p2 + (size_t)c * SS;
    float* t3p = g_t3 + (size_t)plane * SS;
    float* t5p = g_t5 + (size_t)plane * SS;
    __shared__ float sm[SS];
    for (int i = threadIdx.x; i < SS; i += 256) {
        float v = pp[i] * xp[i];
        v *= v;
        sm[i] = v;
        t3p[i] = v;
    }
    __syncthreads();
    int wc = threadIdx.x;              // source column
    if (wc < WWW) {
        float mx = -1e30f;
        for (int h = 0; h < HHH; ++h) mx = fmaxf(mx, sm[h * WWW + wc]);
        float s = 0.f;
        for (int h = 0; h < HHH; ++h) {
            float e = __expf(sm[h * WWW + wc] - mx);
            sm[h * WWW + wc] = e;
            s += e;
        }
        float inv = 1.f / s;
        int wout = (wc + WWW - 1) % WWW;
        for (int h = 0; h < HHH; ++h) {
            int ho = h + 1; if (ho == HHH) ho = 0;
            t5p[ho * WWW + wout] = sm[h * WWW + wc] * inv;
        }
    }
}

// ---------------- prep kernels (weights pre-converted to tf32) ----------------
__global__ void prepW7(const float* __restrict__ w7) {
    int idx = blockIdx.x * 256 + threadIdx.x;     // over 9*256*256
    int o = idx & 255;
    int k = idx >> 8;                              // tap*256 + c
    int tap = k >> 8;
    int cc = k & 255;
    g_w7t[idx] = to_tf32(w7[o * 2304 + cc * 9 + tap]);
}

__global__ void prepW15T(const float* __restrict__ w15) {
    int idx = blockIdx.x * 256 + threadIdx.x;   // c*256 + o
    int o = idx & 255;
    int c = idx >> 8;
    g_w15t[idx] = to_tf32(w15[o * 256 + c]);
}

// veff[c,s] = sum_o (w6[o,c]*p11[o]) * p9[o,s] — block-uniform weights in smem
__global__ void prepVeff(const float* __restrict__ w6, const float* __restrict__ p9,
                         const float* __restrict__ p11) {
    __shared__ float wp[32];
    int c = blockIdx.y;
    int s = blockIdx.x * 256 + threadIdx.x;
    if (threadIdx.x < 32)
        wp[threadIdx.x] = w6[threadIdx.x * CC + c] * p11[threadIdx.x];
    __syncthreads();
    if (s < SS) {
        float acc = 0.f;
#pragma unroll
        for (int o = 0; o < 32; ++o)
            acc = fmaf(wp[o], p9[o * SS + s], acc);
        g_veff[(size_t)c * SS + s] = acc;
    }
}

// ================== convT7 via tf32 mma.sync: M=256, N=3136, K=2304 ==================
__global__ void __launch_bounds__(256) convT7mma(const float* __restrict__ x) {
    __shared__ float As[2][16][136];
    __shared__ float Bs[2][16][136];
    int n = blockIdx.z;
    int m0 = blockIdx.y * 128;
    int col0 = blockIdx.x * 128;       // 25 tiles; last partial
    int t = threadIdx.x;
    int lane = t & 31, wid = t >> 5;
    int warp_m = wid & 1, warp_n = wid >> 1;
    int g = lane >> 2, ti = lane & 3;

    int ak = t >> 5;
    int am4 = (t & 31) * 4;
    int bp = t & 127, kb = (t >> 7) * 8;
    int pglob = col0 + bp;
    bool pin = pglob < SS;
    int h = pin ? pglob / 56 : 0;
    int w = pin ? pglob - h * 56 : 0;
    const float* xn = x + (size_t)n * CS;

    float4 a0r, a1r;
    float br[8];
    float acc[4][4][4] = {};

#define CONV_LOAD(kg) {                                                        \
    int tap = (kg) >> 8; int kin = (kg) & 255;                                 \
    a0r = *(const float4*)&g_w7t[(size_t)((kg) + ak) * 256 + m0 + am4];        \
    a1r = *(const float4*)&g_w7t[(size_t)((kg) + ak + 8) * 256 + m0 + am4];    \
    int dy = (tap / 3) * 3 - 3, dxx = (tap % 3) * 3 - 3;                       \
    int hh = h + dy, ww = w + dxx;                                             \
    bool valid = pin && ((unsigned)hh < 56u) && ((unsigned)ww < 56u);          \
    int poff = hh * 56 + ww;                                                   \
    _Pragma("unroll")                                                          \
    for (int i = 0; i < 8; ++i)                                                \
        br[i] = valid ? xn[(size_t)(kin + kb + i) * SS + poff] : 0.f; }

#define CONV_STORE(buf) {                                                      \
    *(float4*)&As[buf][ak][am4] = a0r;                                         \
    *(float4*)&As[buf][ak + 8][am4] = a1r;                                     \
    _Pragma("unroll")                                                          \
    for (int i = 0; i < 8; ++i) Bs[buf][kb + i][bp] = to_tf32(br[i]); }

    CONV_LOAD(0);
    CONV_STORE(0);
#pragma unroll 1
    for (int kg = 0; kg < 2304; kg += 32) {
        __syncthreads();
        CONV_LOAD(kg + 16);
        MMA_K8((float(*)[136])As[0], (float(*)[136])Bs[0]);
        MMA_K8((float(*)[136])(As[0] + 8), (float(*)[136])(Bs[0] + 8));
        CONV_STORE(1);
        __syncthreads();
        bool more = (kg + 32) < 2304;
        if (more) CONV_LOAD(kg + 32);
        MMA_K8((float(*)[136])As[1], (float(*)[136])Bs[1]);
        MMA_K8((float(*)[136])(As[1] + 8), (float(*)[136])(Bs[1] + 8));
        if (more) CONV_STORE(0);
    }
#undef CONV_LOAD
#undef CONV_STORE

    float* t7n = g_t7 + (size_t)n * CS;
#pragma unroll
    for (int mi = 0; mi < 4; ++mi) {
#pragma unroll
        for (int ni = 0; ni < 4; ++ni) {
            int row = m0 + warp_m * 64 + mi * 16 + g;
            int col = col0 + warp_n * 32 + ni * 8 + 2 * ti;
            if (col < SS) {
                *(float2*)&t7n[(size_t)row * SS + col] =
                    make_float2(acc[mi][ni][0], acc[mi][ni][1]);
                *(float2*)&t7n[(size_t)(row + 8) * SS + col] =
                    make_float2(acc[mi][ni][2], acc[mi][ni][3]);
            }
        }
    }
}

// ================== NT GEMM via mma + split-K: Part = A @ B^T (chunk) ==================
__global__ void __launch_bounds__(256) gemmNTmma(const float* __restrict__ A,
                                                 const float* __restrict__ B,
                                                 float* __restrict__ Part,
                                                 size_t strA, size_t strB) {
    __shared__ float As[2][8][136];
    __shared__ float Bs[2][8][136];
    int z = blockIdx.z;
    int n = z >> 2, split = z & 3;
    int kbeg = split * 784;
    const float* An = A + (size_t)n * strA;
    const float* Bn = B + (size_t)n * strB;
    float* P = Part + (size_t)z * 65536;
    int m0 = blockIdx.y * 128, n0 = blockIdx.x * 128;
    int t = threadIdx.x;
    int lane = t & 31, wid = t >> 5;
    int warp_m = wid & 1, warp_n = wid >> 1;
    int g = lane >> 2, ti = lane & 3;
    int row = t & 127, kq = (t >> 7) * 4;
    float4 a_reg, b_reg;
    float acc[4][4][4] = {};

#define NT_LOAD(k0) {                                                          \
    a_reg = *(const float4*)&An[(size_t)(m0 + row) * SS + (k0) + kq];          \
    b_reg = *(const float4*)&Bn[(size_t)(n0 + row) * SS + (k0) + kq]; }

#define NT_STORE(buf) {                                                        \
    As[buf][kq + 0][row] = to_tf32(a_reg.x);                                   \
    As[buf][kq + 1][row] = to_tf32(a_reg.y);                                   \
    As[buf][kq + 2][row] = to_tf32(a_reg.z);                                   \
    As[buf][kq + 3][row] = to_tf32(a_reg.w);                                   \
    Bs[buf][kq + 0][row] = to_tf32(b_reg.x);                                   \
    Bs[buf][kq + 1][row] = to_tf32(b_reg.y);                                   \
    Bs[buf][kq + 2][row] = to_tf32(b_reg.z);                                   \
    Bs[buf][kq + 3][row] = to_tf32(b_reg.w); }

    NT_LOAD(kbeg);
    NT_STORE(0);
#pragma unroll 1
    for (int k0 = kbeg; k0 < kbeg + 784; k0 += 16) {
        __syncthreads();
        NT_LOAD(k0 + 8);
        MMA_K8(As[0], Bs[0]);
        NT_STORE(1);
        __syncthreads();
        bool more = (k0 + 16) < kbeg + 784;
        if (more) NT_LOAD(k0 + 16);
        MMA_K8(As[1], Bs[1]);
        if (more) NT_STORE(0);
    }
#undef NT_LOAD
#undef NT_STORE

#pragma unroll
    for (int mi = 0; mi < 4; ++mi) {
#pragma unroll
        for (int ni = 0; ni < 4; ++ni) {
            int r = m0 + warp_m * 64 + mi * 16 + g;
            int c = n0 + warp_n * 32 + ni * 8 + 2 * ti;
            *(float2*)&P[(size_t)r * 256 + c] =
                make_float2(acc[mi][ni][0], acc[mi][ni][1]);
            *(float2*)&P[(size_t)(r + 8) * 256 + c] =
                make_float2(acc[mi][ni][2], acc[mi][ni][3]);
        }
    }
}

// ---------------- reduce split-K partials ----------------
__global__ void ntReduce(const float* __restrict__ Part, float* __restrict__ Out,
                         float scale) {
    int idx = blockIdx.x * 256 + threadIdx.x;   // over NB*65536
    int nb = idx >> 16;
    int r = idx & 65535;
    float s = 0.f;
#pragma unroll
    for (int sp = 0; sp < 4; ++sp)
        s += Part[(size_t)(nb * 4 + sp) * 65536 + r];
    Out[idx] = s * scale;
}

// ================== NN GEMM via mma, K=256, N=3136: two fused modes ==================
// MODE 0: A=w15t (pre-tf32, no batch), B = x rolled(+1,h); out t17 = t3 - acc
// MODE 1: A=t19 (k-major, cvt), B = t13; out = s_c*acc + t7*t17 -> final output
template <int MODE>
__global__ void __launch_bounds__(256) gemmNNmma(const float* __restrict__ A,
                                                 const float* __restrict__ B,
                                                 float* __restrict__ Out,
                                                 const float* __restrict__ E1,
                                                 const float* __restrict__ E2) {
    __shared__ float As[2][8][136];
    __shared__ float Bs[2][8][136];
    int n = blockIdx.z;
    int m0 = blockIdx.y * 128;
    int col0 = blockIdx.x * 128;
    const float* An = (MODE == 0) ? A : A + (size_t)n * 65536;
    const float* Bn = B + (size_t)n * CS;
    int t = threadIdx.x;
    int lane = t & 31, wid = t >> 5;
    int warp_m = wid & 1, warp_n = wid >> 1;
    int g = lane >> 2, ti = lane & 3;
    int ak = t >> 5, am4 = (t & 31) * 4;      // A: row ak (k), 4 m cols
    int bp = t & 127, kb = (t >> 7) * 4;      // B: pixel bp, k rows kb..kb+3
    int pglob = col0 + bp;
    bool pin = pglob < SS;
    int poff;
    if (MODE == 0) {
        int pg = pin ? pglob : 0;
        int hh = pg / 56, ww = pg - hh * 56;
        int h2 = hh ? hh - 1 : 55;            // t14[h] = x[h-1 mod 56]
        poff = h2 * 56 + ww;
    } else {
        poff = pin ? pglob : 0;
    }
    float4 a_reg; float br[4];
    float acc[4][4][4] = {};

#define FN_LOAD(k0) {                                                          \
    a_reg = *(const float4*)&An[(size_t)((k0) + ak) * 256 + m0 + am4];         \
    _Pragma("unroll")                                                          \
    for (int i = 0; i < 4; ++i)                                                \
        br[i] = Bn[(size_t)((k0) + kb + i) * SS + poff]; }

#define FN_STORE(buf) {                                                        \
    if (MODE == 0) { *(float4*)&As[buf][ak][am4] = a_reg; }                    \
    else {                                                                     \
        As[buf][ak][am4 + 0] = to_tf32(a_reg.x);                               \
        As[buf][ak][am4 + 1] = to_tf32(a_reg.y);                               \
        As[buf][ak][am4 + 2] = to_tf32(a_reg.z);                               \
        As[buf][ak][am4 + 3] = to_tf32(a_reg.w);                               \
    }                                                                          \
    _Pragma("unroll")                                                          \
    for (int i = 0; i < 4; ++i) Bs[buf][kb + i][bp] = to_tf32(br[i]); }

    FN_LOAD(0);
    FN_STORE(0);
#pragma unroll 1
    for (int k0 = 0; k0 < 256; k0 += 16) {
        __syncthreads();
        FN_LOAD(k0 + 8);
        MMA_K8(As[0], Bs[0]);
        FN_STORE(1);
        __syncthreads();
        bool more = (k0 + 16) < 256;
        if (more) FN_LOAD(k0 + 16);
        MMA_K8(As[1], Bs[1]);
        if (more) FN_STORE(0);
    }
#undef FN_LOAD
#undef FN_STORE

    float* on = Out + (size_t)n * CS;
#pragma unroll
    for (int mi = 0; mi < 4; ++mi) {
#pragma unroll
        for (int ni = 0; ni < 4; ++ni) {
            int row = m0 + warp_m * 64 + mi * 16 + g;
            int col = col0 + warp_n * 32 + ni * 8 + 2 * ti;
            if (col < SS) {
                size_t i0 = (size_t)row * SS + col;
                size_t i1 = (size_t)(row + 8) * SS + col;
                if (MODE == 0) {
                    const float* e1 = E1 + (size_t)n * CS;   // t3
                    float2 e0 = *(const float2*)&e1[i0];
                    *(float2*)&on[i0] = make_float2(e0.x - acc[mi][ni][0],
                                                    e0.y - acc[mi][ni][1]);
                    float2 e1v = *(const float2*)&e1[i1];
                    *(float2*)&on[i1] = make_float2(e1v.x - acc[mi][ni][2],
                                                    e1v.y - acc[mi][ni][3]);
                } else {
                    const float* e1 = E1 + (size_t)n * CS;   // t7
                    const float* e2 = E2 + (size_t)n * CS;   // t17
                    const float sc = 0.0625f;                // 1/sqrt(256)
                    float2 a7 = *(const float2*)&e1[i0];
                    float2 a17 = *(const float2*)&e2[i0];
                    float2 r0;
                    r0.x = fmaf(sc, acc[mi][ni][0], a7.x * a17.x);
                    r0.y = fmaf(sc, acc[mi][ni][1], a7.y * a17.y);
                    *(float2*)&on[i0] = r0;
                    float2 b7 = *(const float2*)&e1[i1];
                    float2 b17 = *(const float2*)&e2[i1];
                    float2 r1;
                    r1.x = fmaf(sc, acc[mi][ni][2], b7.x * b17.x);
                    r1.y = fmaf(sc, acc[mi][ni][3], b7.y * b17.y);
                    *(float2*)&on[i1] = r1;
                }
            }
        }
    }
}

// ---------------- small NN GEMM 64x64/4x4: t19 = s_hw * Amat @ t8 ----------------
__global__ void __launch_bounds__(256) gemmT19(const float* __restrict__ A,
                                               const float* __restrict__ B,
                                               float* __restrict__ Out) {
    __shared__ float As[16][68];
    __shared__ float Bs[16][64];
    int n = blockIdx.z;
    int m0 = blockIdx.y * 64;
    int col0 = blockIdx.x * 64;
    const float* An = A + (size_t)n * 65536;
    const float* Bn = B + (size_t)n * 65536;
    int t = threadIdx.x;
    int tx = t & 15, ty = t >> 4;
    int am = t >> 2;
    int akq = (t & 3) * 4;
    int bp = t & 63;
    int bk = t >> 6;
    float acc[4][4] = {};
    for (int k0 = 0; k0 < 256; k0 += 16) {
        float4 a = *(const float4*)&An[(size_t)(m0 + am) * 256 + k0 + akq];
        float bv[4];
#pragma unroll
        for (int ps = 0; ps < 4; ++ps)
            bv[ps] = Bn[(size_t)(k0 + bk + 4 * ps) * 256 + col0 + bp];
        __syncthreads();
        As[akq + 0][am] = a.x;
        As[akq + 1][am] = a.y;
        As[akq + 2][am] = a.z;
        As[akq + 3][am] = a.w;
#pragma unroll
        for (int ps = 0; ps < 4; ++ps) Bs[bk + 4 * ps][bp] = bv[ps];
        __syncthreads();
#pragma unroll
        for (int kk = 0; kk < 16; ++kk) {
            float av[4], bw[4];
            *(float4*)av = *(const float4*)&As[kk][ty * 4];
            *(float4*)bw = *(const float4*)&Bs[kk][tx * 4];
#pragma unroll
            for (int i = 0; i < 4; ++i)
#pragma unroll
                for (int j = 0; j < 4; ++j) acc[i][j] = fmaf(av[i], bw[j], acc[i][j]);
        }
    }
    float* on = Out + (size_t)n * 65536;
    const float shw = 1.f / 56.f;
#pragma unroll
    for (int i = 0; i < 4; ++i)
        *(float4*)&on[(size_t)(m0 + ty * 4 + i) * 256 + col0 + tx * 4] =
            make_float4(acc[i][0] * shw, acc[i][1] * shw,
                        acc[i][2] * shw, acc[i][3] * shw);
}

// ---------------- t11[n,s] = sum_c t3[n,c,s]*veff[c,s] ----------------
__global__ void calcT11() {
    int idx = blockIdx.x * 256 + threadIdx.x;   // n*SS + s
    int n = idx / SS;
    int s = idx - n * SS;
    const float* t3n = g_t3 + (size_t)n * CS + s;
    const float* vf = g_veff + s;
    float acc = 0.f;
#pragma unroll 8
    for (int c = 0; c < CC; ++c)
        acc = fmaf(t3n[(size_t)c * SS], vf[(size_t)c * SS], acc);
    g_t11[idx] = acc;
}

// ---------------- t13 = t11 - dwconv3x1_d2(max(t5,t7)) — fused per-plane smem ----------------
__global__ void __launch_bounds__(256) calcT13(const float* __restrict__ w12) {
    int plane = blockIdx.x;           // n*256 + c
    int c = plane & 255, n = plane >> 8;
    __shared__ float sm[SS];
    const float* t5p = g_t5 + (size_t)plane * SS;
    const float* t7p = g_t7 + (size_t)plane * SS;
    for (int i = threadIdx.x; i < SS; i += 256)
        sm[i] = fmaxf(t5p[i], t7p[i]);
    __syncthreads();
    float w0 = w12[c * 3 + 0], w1 = w12[c * 3 + 1], w2 = w12[c * 3 + 2];
    const float* t11n = g_t11 + (size_t)n * SS;
    float* o = g_t13 + (size_t)plane * SS;
    for (int i = threadIdx.x; i < SS; i += 256) {
        float acc = w1 * sm[i];
        if (i >= 112) acc = fmaf(w0, sm[i - 112], acc);
        if (i < SS - 112) acc = fmaf(w2, sm[i + 112], acc);
        o[i] = t11n[i] - acc;
    }
}

// ---------------- launch ----------------
extern "C" void kernel_launch(void* const* d_in, const int* in_sizes, int n_in,
                              void* d_out, int out_size) {
    const float* x   = (const float*)d_in[0];
    const float* p2  = (const float*)d_in[1];
    const float* w6  = (const float*)d_in[2];
    const float* w7  = (const float*)d_in[3];
    const float* p9  = (const float*)d_in[4];
    const float* p11 = (const float*)d_in[5];
    const float* w12 = (const float*)d_in[6];
    const float* w15 = (const float*)d_in[7];
    const float* p16 = (const float*)d_in[8];
    float* out = (float*)d_out;

    void *t3p, *t5p, *t7p, *t17p, *t13p, *t8p, *Amatp, *t19p, *w15tp, *partp;
    cudaGetSymbolAddress(&t3p, g_t3);
    cudaGetSymbolAddress(&t5p, g_t5);
    cudaGetSymbolAddress(&t7p, g_t7);
    cudaGetSymbolAddress(&t17p, g_t17);
    cudaGetSymbolAddress(&t13p, g_t13);
    cudaGetSymbolAddress(&t8p, g_t8);
    cudaGetSymbolAddress(&Amatp, g_Amat);
    cudaGetSymbolAddress(&t19p, g_t19);
    cudaGetSymbolAddress(&w15tp, g_w15t);
    cudaGetSymbolAddress(&partp, g_part);

    // stage A: t3, t5
    stageA<<<NB * CC, 256>>>(x, p2);
    // weight prep (independent)
    prepW7<<<9 * CC, 256>>>(w7);
    prepW15T<<<CC, 256>>>(w15);
    prepVeff<<<dim3(13, 256), 256>>>(w6, p9, p11);
    // t7: implicit-GEMM conv on tensor cores (tf32 mma.sync)
    convT7mma<<<dim3(25, 2, NB), 256>>>(x);
    // t17 = t3 - w15 @ roll(x, +1, h)  (tf32 mma, fused epilogue)
    gemmNNmma<0><<<dim3(25, 2, NB), 256>>>((const float*)w15tp, x, (float*)t17p,
                                           (const float*)t3p, nullptr);
    // t8 = s_hw * t5 @ t3^T  (tf32 mma, split-K 4 + reduce)
    gemmNTmma<<<dim3(2, 2, NB * 4), 256>>>((const float*)t5p, (const float*)t3p,
                                           (float*)partp, (size_t)CS, (size_t)CS);
    ntReduce<<<NB * 256, 256>>>((const float*)partp, (float*)t8p, 1.f / 56.f);
    // t11, t13
    calcT11<<<(NB * SS) / 256, 256>>>();
    calcT13<<<NB * CC, 256>>>(w12);
    // Amat = t17 @ p16^T  (tf32 mma, split-K 4 + reduce)
    gemmNTmma<<<dim3(2, 2, NB * 4), 256>>>((const float*)t17p, p16,
                                           (float*)partp, (size_t)CS, (size_t)0);
    ntReduce<<<NB * 256, 256>>>((const float*)partp, (float*)Amatp, 1.f);
    // t19 = s_hw * Amat @ t8 (natural layout = k-major A for the final GEMM)
    gemmT19<<<dim3(4, 4, NB), 256>>>((const float*)Amatp, (const float*)t8p,
                                     (float*)t19p);
    // out = s_c * t19(k-major) @ t13 + t7 * t17  (tf32 mma, fused epilogue)
    gemmNNmma<1><<<dim3(25, 2, NB), 256>>>((const float*)t19p, (const float*)t13p, out,
                                           (const float*)t7p, (const float*)t17p);
}